// round 1
// baseline (speedup 1.0000x reference)
#include <cuda_runtime.h>

#define BB 4
#define TT 2048
#define HH 16
#define DKk 64
#define DM 1024

// Scratch (static device globals: allocation-free, graph-capture safe)
__device__ float g_q[BB * HH * TT * DKk];   // [B,H,T,Dk], pre-scaled by 1/sqrt(Dk)
__device__ float g_k[BB * HH * TT * DKk];   // [B,H,T,Dk]
__device__ float g_v[BB * HH * TT * DKk];   // [B,H,T,Dk]
__device__ float g_ao[BB * TT * DM];        // [B,T,D] attention output (pre-Wo)

// ---------------------------------------------------------------------------
// C = (X @ W^T + bias) * scale
// X: [M,K] row-major. W: [N,K] row-major (so this is X @ W.T).
// HEAD_LAYOUT=1: write to [B,H,T,Dk] with b=m/T, t=m%T, h=n/64, dk=n%64.
// HEAD_LAYOUT=0: write to [M,N] row-major.
// Block tile: 128(M) x 64(N), BK=16. 256 threads, 8x4 micro-tile per thread.
// ---------------------------------------------------------------------------
template <int HEAD_LAYOUT>
__global__ __launch_bounds__(256)
void gemm_bias_kernel(const float* __restrict__ X, const float* __restrict__ W,
                      const float* __restrict__ bias, float* __restrict__ out,
                      int M, int N, int K, float scale)
{
    __shared__ float As[128][17];   // pad 17 -> ty-pairs hit different banks
    __shared__ float Bs[16][64];    // [k][n], read as float4 (conflict-free)

    const int tid = threadIdx.x;
    const int ty = tid >> 4;        // 0..15 -> rows 8*ty .. 8*ty+7
    const int tx = tid & 15;        // 0..15 -> cols 4*tx .. 4*tx+3
    const int m0 = blockIdx.y * 128;
    const int n0 = blockIdx.x * 64;

    float acc[8][4];
#pragma unroll
    for (int i = 0; i < 8; i++)
#pragma unroll
        for (int j = 0; j < 4; j++) acc[i][j] = 0.0f;

    for (int k0 = 0; k0 < K; k0 += 16) {
        // Load A tile: 128 rows x 16 cols = 512 float4, 2 per thread
        {
            int r = tid >> 2;               // 0..63
            int c = (tid & 3) * 4;          // 0,4,8,12
#pragma unroll
            for (int rr = r; rr < 128; rr += 64) {
                float4 v = *(const float4*)&X[(size_t)(m0 + rr) * K + k0 + c];
                As[rr][c + 0] = v.x; As[rr][c + 1] = v.y;
                As[rr][c + 2] = v.z; As[rr][c + 3] = v.w;
            }
        }
        // Load W tile transposed into Bs[k][n]: 64 n-rows x 16 k = 1 float4/thread
        {
            int n = tid >> 2;               // 0..63
            int c = (tid & 3) * 4;          // k offset
            float4 v = *(const float4*)&W[(size_t)(n0 + n) * K + k0 + c];
            Bs[c + 0][n] = v.x; Bs[c + 1][n] = v.y;
            Bs[c + 2][n] = v.z; Bs[c + 3][n] = v.w;
        }
        __syncthreads();

#pragma unroll
        for (int k = 0; k < 16; k++) {
            float4 bv = *(const float4*)&Bs[k][tx * 4];
            float b[4] = {bv.x, bv.y, bv.z, bv.w};
            float a[8];
#pragma unroll
            for (int i = 0; i < 8; i++) a[i] = As[ty * 8 + i][k];
#pragma unroll
            for (int i = 0; i < 8; i++)
#pragma unroll
                for (int j = 0; j < 4; j++)
                    acc[i][j] = fmaf(a[i], b[j], acc[i][j]);
        }
        __syncthreads();
    }

    // Epilogue
#pragma unroll
    for (int i = 0; i < 8; i++) {
        int m = m0 + ty * 8 + i;
#pragma unroll
        for (int j = 0; j < 4; j++) {
            int n = n0 + tx * 4 + j;
            float val = (acc[i][j] + bias[n]) * scale;
            if (HEAD_LAYOUT) {
                int b = m / TT, t = m % TT;
                int h = n / DKk, dk = n % DKk;
                out[(((size_t)b * HH + h) * TT + t) * DKk + dk] = val;
            } else {
                out[(size_t)m * N + n] = val;
            }
        }
    }
}

// ---------------------------------------------------------------------------
// Flash attention, fp32, causal. Q pre-scaled by 1/sqrt(Dk).
// Grid: (T/64 q-tiles, B*H). 256 threads.
// Per block: 64 q-rows, streamed 32-row KV tiles with online softmax.
// Thread (ty,tx) in 16x16: S rows 4ty..+3 x cols 2tx..+1; O rows 4ty..+3 x dk 4tx..+3
// ---------------------------------------------------------------------------
__global__ __launch_bounds__(256)
void flash_attn_kernel(const float* __restrict__ Q, const float* __restrict__ K,
                       const float* __restrict__ V, float* __restrict__ out)
{
    __shared__ float Qs[64][65];
    __shared__ float Ks[32][65];
    __shared__ float Vs[32][64];
    __shared__ float Ss[64][33];
    __shared__ float row_m[64], row_l[64], row_alpha[64];

    const int tid = threadIdx.x;
    const int ty = tid >> 4;
    const int tx = tid & 15;
    const int qt = blockIdx.x;          // q tile (64 rows)
    const int bh = blockIdx.y;          // b*H + h

    const float* Qb = Q + (size_t)bh * TT * DKk;
    const float* Kb = K + (size_t)bh * TT * DKk;
    const float* Vb = V + (size_t)bh * TT * DKk;

    // Load Q tile: 64x64 = 1024 float4, 4 per thread
#pragma unroll
    for (int it = 0; it < 4; it++) {
        int s = tid + it * 256;
        int r = s >> 4;
        int c = (s & 15) * 4;
        float4 v = *(const float4*)&Qb[(size_t)(qt * 64 + r) * DKk + c];
        Qs[r][c + 0] = v.x; Qs[r][c + 1] = v.y;
        Qs[r][c + 2] = v.z; Qs[r][c + 3] = v.w;
    }
    if (tid < 64) { row_m[tid] = -1e30f; row_l[tid] = 0.0f; }

    float accO[4][4];
#pragma unroll
    for (int i = 0; i < 4; i++)
#pragma unroll
        for (int j = 0; j < 4; j++) accO[i][j] = 0.0f;

    __syncthreads();

    const int nkt = 2 * qt + 2;     // 32-wide kv tiles covering causal range
    for (int kt = 0; kt < nkt; kt++) {
        // Load K,V tiles: 32x64 = 512 float4 each, 2 per thread each
#pragma unroll
        for (int it = 0; it < 2; it++) {
            int s = tid + it * 256;
            int r = s >> 4;
            int c = (s & 15) * 4;
            float4 kv = *(const float4*)&Kb[(size_t)(kt * 32 + r) * DKk + c];
            Ks[r][c + 0] = kv.x; Ks[r][c + 1] = kv.y;
            Ks[r][c + 2] = kv.z; Ks[r][c + 3] = kv.w;
            float4 vv = *(const float4*)&Vb[(size_t)(kt * 32 + r) * DKk + c];
            *(float4*)&Vs[r][c] = vv;
        }
        __syncthreads();

        // S = Qs @ Ks^T  (Q already scaled)
        float sacc[4][2];
#pragma unroll
        for (int i = 0; i < 4; i++) { sacc[i][0] = 0.0f; sacc[i][1] = 0.0f; }
#pragma unroll 8
        for (int k = 0; k < 64; k++) {
            float b0 = Ks[2 * tx + 0][k];
            float b1 = Ks[2 * tx + 1][k];
#pragma unroll
            for (int i = 0; i < 4; i++) {
                float a = Qs[4 * ty + i][k];
                sacc[i][0] = fmaf(a, b0, sacc[i][0]);
                sacc[i][1] = fmaf(a, b1, sacc[i][1]);
            }
        }
        // causal mask + store to shared
#pragma unroll
        for (int i = 0; i < 4; i++) {
            int qg = qt * 64 + 4 * ty + i;
#pragma unroll
            for (int j = 0; j < 2; j++) {
                int kg = kt * 32 + 2 * tx + j;
                Ss[4 * ty + i][2 * tx + j] = (kg <= qg) ? sacc[i][j] : -1e30f;
            }
        }
        __syncthreads();

        // Online softmax: one thread per q row
        if (tid < 64) {
            int r = tid;
            float m_old = row_m[r];
            float m = m_old;
#pragma unroll 8
            for (int c = 0; c < 32; c++) m = fmaxf(m, Ss[r][c]);
            float alpha = __expf(m_old - m);
            float sum = 0.0f;
#pragma unroll 8
            for (int c = 0; c < 32; c++) {
                float p = __expf(Ss[r][c] - m);
                Ss[r][c] = p;
                sum += p;
            }
            row_m[r] = m;
            row_l[r] = row_l[r] * alpha + sum;
            row_alpha[r] = alpha;
        }
        __syncthreads();

        // Rescale O and accumulate P @ V
        float al[4];
#pragma unroll
        for (int i = 0; i < 4; i++) al[i] = row_alpha[4 * ty + i];
#pragma unroll
        for (int i = 0; i < 4; i++)
#pragma unroll
            for (int j = 0; j < 4; j++) accO[i][j] *= al[i];
#pragma unroll 8
        for (int k = 0; k < 32; k++) {
            float4 bv = *(const float4*)&Vs[k][4 * tx];
            float b[4] = {bv.x, bv.y, bv.z, bv.w};
#pragma unroll
            for (int i = 0; i < 4; i++) {
                float a = Ss[4 * ty + i][k];
                accO[i][0] = fmaf(a, b[0], accO[i][0]);
                accO[i][1] = fmaf(a, b[1], accO[i][1]);
                accO[i][2] = fmaf(a, b[2], accO[i][2]);
                accO[i][3] = fmaf(a, b[3], accO[i][3]);
            }
        }
        __syncthreads();
    }

    // Epilogue: divide by l, write [B,T,D] layout
    const int b = bh >> 4;
    const int h = bh & 15;
#pragma unroll
    for (int i = 0; i < 4; i++) {
        int qg = qt * 64 + 4 * ty + i;
        float linv = 1.0f / row_l[4 * ty + i];
        float4 o;
        o.x = accO[i][0] * linv;
        o.y = accO[i][1] * linv;
        o.z = accO[i][2] * linv;
        o.w = accO[i][3] * linv;
        *(float4*)&out[((size_t)b * TT + qg) * DM + h * DKk + 4 * tx] = o;
    }
}

// ---------------------------------------------------------------------------
extern "C" void kernel_launch(void* const* d_in, const int* in_sizes, int n_in,
                              void* d_out, int out_size)
{
    const float* query = (const float*)d_in[0];
    const float* key   = (const float*)d_in[1];
    const float* value = (const float*)d_in[2];
    // d_in[3] = mask (causal tril, known statically — unused)
    const float* Wq = (const float*)d_in[4];
    const float* bq = (const float*)d_in[5];
    const float* Wk = (const float*)d_in[6];
    const float* bk = (const float*)d_in[7];
    const float* Wv = (const float*)d_in[8];
    const float* bv = (const float*)d_in[9];
    const float* Wo = (const float*)d_in[10];
    const float* bo = (const float*)d_in[11];
    float* out = (float*)d_out;

    float *q, *k, *v, *ao;
    cudaGetSymbolAddress((void**)&q,  g_q);
    cudaGetSymbolAddress((void**)&k,  g_k);
    cudaGetSymbolAddress((void**)&v,  g_v);
    cudaGetSymbolAddress((void**)&ao, g_ao);

    const int M = BB * TT;  // 8192
    dim3 gemm_grid(DM / 64, M / 128);   // (16, 64)

    // QKV projections (Q pre-scaled by 1/sqrt(Dk) = 0.125)
    gemm_bias_kernel<1><<<gemm_grid, 256>>>(query, Wq, bq, q, M, DM, DM, 0.125f);
    gemm_bias_kernel<1><<<gemm_grid, 256>>>(key,   Wk, bk, k, M, DM, DM, 1.0f);
    gemm_bias_kernel<1><<<gemm_grid, 256>>>(value, Wv, bv, v, M, DM, DM, 1.0f);

    // Flash attention (causal)
    dim3 fa_grid(TT / 64, BB * HH);     // (32, 64)
    flash_attn_kernel<<<fa_grid, 256>>>(q, k, v, ao);

    // Output projection
    gemm_bias_kernel<0><<<gemm_grid, 256>>>(ao, Wo, bo, out, M, DM, DM, 1.0f);
}

// round 3
// speedup vs baseline: 1.6829x; 1.6829x over previous
#include <cuda_runtime.h>
#include <cstdint>

#define BB 4
#define TT 2048
#define HH 16
#define DKk 64
#define DM 1024

// Scratch (static device globals: allocation-free, graph-capture safe)
__device__ float g_q[BB * HH * TT * DKk];   // [B,H,T,Dk], pre-scaled by 1/sqrt(Dk)
__device__ float g_k[BB * HH * TT * DKk];   // [B,H,T,Dk]
__device__ float g_v[BB * HH * TT * DKk];   // [B,H,T,Dk]
__device__ float g_ao[BB * TT * DM];        // [B,T,D] attention output (pre-Wo)

// ---------------------------------------------------------------------------
// Baseline-PTX helpers (NO sm_103a-gated instructions: harness ptxas targets
// plain sm_103, so tcgen05/TMEM are unavailable; mma.sync + cp.async are fine)
// ---------------------------------------------------------------------------
__device__ __forceinline__ void cp_async16(uint32_t s, const void* g) {
    asm volatile("cp.async.cg.shared.global [%0], [%1], 16;\n" :: "r"(s), "l"(g));
}
__device__ __forceinline__ void cp_commit() {
    asm volatile("cp.async.commit_group;\n" ::: "memory");
}
__device__ __forceinline__ void cp_wait2() {
    asm volatile("cp.async.wait_group 2;\n" ::: "memory");
}

__device__ __forceinline__ uint32_t f2tf32(float x) {
    uint32_t r;
    asm("cvt.rna.tf32.f32 %0, %1;" : "=r"(r) : "f"(x));
    return r;
}

// D += A(16x8 tf32, row) * B(8x8 tf32, col)
__device__ __forceinline__ void mma_tf32(float* c, const uint32_t* a, const uint32_t* b) {
    asm volatile(
        "mma.sync.aligned.m16n8k8.row.col.f32.tf32.tf32.f32 "
        "{%0,%1,%2,%3}, {%4,%5,%6,%7}, {%8,%9}, {%0,%1,%2,%3};"
        : "+f"(c[0]), "+f"(c[1]), "+f"(c[2]), "+f"(c[3])
        : "r"(a[0]), "r"(a[1]), "r"(a[2]), "r"(a[3]), "r"(b[0]), "r"(b[1]));
}

// ---------------------------------------------------------------------------
// Tensor-core tf32 GEMM: C = (X @ W^T + bias) * scale
// X: [M,K] rm.  W: [N,K] rm (== col-major B for row.col mma).
// CTA tile 128x128, BK=32, 4-stage cp.async pipeline, 8 warps (2x4),
// warp tile 64x32, mma.sync m16n8k8 tf32.
// Smem stride 36 floats: fragment-load banks = 4*group + tig -> conflict-free.
// HEAD_LAYOUT=1: scatter to [B,H,T,Dk]; else row-major [M,N].
// ---------------------------------------------------------------------------
#define SROW 36
#define STAGE_FLOATS (2 * 128 * SROW)                  // A tile + B tile
#define GEMM_SMEM_BYTES (4 * STAGE_FLOATS * 4)         // 4 stages = 147456 B

template <int HEAD_LAYOUT>
__global__ __launch_bounds__(256)
void gemm_tf32_kernel(const float* __restrict__ X, const float* __restrict__ W,
                      const float* __restrict__ bias, float* __restrict__ out,
                      int M, int N, int K, float scale)
{
    extern __shared__ float smem[];
    const uint32_t smem_base = (uint32_t)__cvta_generic_to_shared(smem);
    const int tid = threadIdx.x;
    const int wid = tid >> 5;
    const int lane = tid & 31;
    const int g = lane >> 2;          // groupID 0..7
    const int tig = lane & 3;         // thread-in-group 0..3
    const int wm = wid >> 2;          // warp m 0..1  (64 rows)
    const int wn = wid & 3;           // warp n 0..3  (32 cols)
    const int m0 = blockIdx.y * 128;
    const int n0 = blockIdx.x * 128;
    const int KT = K >> 5;            // 32-wide K tiles

    // 8 cp.async16 per thread per stage (A: 128x8 chunks, B: 128x8 chunks)
    auto load_tile = [&](int tile) {
        const int k0 = tile << 5;
        const uint32_t base = smem_base + (uint32_t)(tile & 3) * (STAGE_FLOATS * 4);
#pragma unroll
        for (int i = 0; i < 4; i++) {
            int idx = tid + (i << 8);          // 0..1023
            int r = idx >> 3;                  // row 0..127
            int c = idx & 7;                   // 16B chunk 0..7
            uint32_t dst = base + (uint32_t)(r * SROW * 4 + c * 16);
            cp_async16(dst, X + (size_t)(m0 + r) * K + k0 + c * 4);
            cp_async16(dst + 128 * SROW * 4, W + (size_t)(n0 + r) * K + k0 + c * 4);
        }
    };

#pragma unroll
    for (int t = 0; t < 3; t++) { load_tile(t); cp_commit(); }

    float acc[4][4][4];
#pragma unroll
    for (int fm = 0; fm < 4; fm++)
#pragma unroll
        for (int fn = 0; fn < 4; fn++)
#pragma unroll
            for (int e = 0; e < 4; e++) acc[fm][fn][e] = 0.0f;

    for (int kt = 0; kt < KT; kt++) {
        cp_wait2();            // tile kt resident (tiles kt+1, kt+2 may be pending)
        __syncthreads();       // all warps see it; all done with slot (kt-1)&3
        if (kt + 3 < KT) load_tile(kt + 3);   // slot (kt+3)&3 == (kt-1)&3
        cp_commit();           // uniform group count (possibly empty)

        const float* sA = smem + (size_t)(kt & 3) * STAGE_FLOATS;
        const float* sB = sA + 128 * SROW;

#pragma unroll
        for (int ks = 0; ks < 4; ks++) {
            const int kb = ks * 8;
            uint32_t a[4][4];
#pragma unroll
            for (int fm = 0; fm < 4; fm++) {
                const float* ar = sA + (wm * 64 + fm * 16 + g) * SROW + kb + tig;
                a[fm][0] = f2tf32(ar[0]);
                a[fm][1] = f2tf32(ar[8 * SROW]);
                a[fm][2] = f2tf32(ar[4]);
                a[fm][3] = f2tf32(ar[8 * SROW + 4]);
            }
            uint32_t b[4][2];
#pragma unroll
            for (int fn = 0; fn < 4; fn++) {
                const float* br = sB + (wn * 32 + fn * 8 + g) * SROW + kb + tig;
                b[fn][0] = f2tf32(br[0]);
                b[fn][1] = f2tf32(br[4]);
            }
#pragma unroll
            for (int fm = 0; fm < 4; fm++)
#pragma unroll
                for (int fn = 0; fn < 4; fn++)
                    mma_tf32(acc[fm][fn], a[fm], b[fn]);
        }
    }

    // Epilogue: c0,c1 -> (row g, cols 2tig,2tig+1); c2,c3 -> (row g+8)
#pragma unroll
    for (int fm = 0; fm < 4; fm++) {
#pragma unroll
        for (int fn = 0; fn < 4; fn++) {
            int n = n0 + wn * 32 + fn * 8 + 2 * tig;
            float bx = __ldg(&bias[n]);
            float by = __ldg(&bias[n + 1]);
#pragma unroll
            for (int half = 0; half < 2; half++) {
                int m = m0 + wm * 64 + fm * 16 + g + half * 8;
                float2 o;
                o.x = (acc[fm][fn][half * 2 + 0] + bx) * scale;
                o.y = (acc[fm][fn][half * 2 + 1] + by) * scale;
                if (HEAD_LAYOUT) {
                    int b = m / TT, t = m % TT;
                    int h = n / DKk, dk = n % DKk;
                    *(float2*)&out[(((size_t)b * HH + h) * TT + t) * DKk + dk] = o;
                } else {
                    *(float2*)&out[(size_t)m * N + n] = o;
                }
            }
        }
    }
}

// ---------------------------------------------------------------------------
// Flash attention, fp32, causal (unchanged from round 1). Q pre-scaled.
// ---------------------------------------------------------------------------
__global__ __launch_bounds__(256)
void flash_attn_kernel(const float* __restrict__ Q, const float* __restrict__ K,
                       const float* __restrict__ V, float* __restrict__ out)
{
    __shared__ float Qs[64][65];
    __shared__ float Ks[32][65];
    __shared__ float Vs[32][64];
    __shared__ float Ss[64][33];
    __shared__ float row_m[64], row_l[64], row_alpha[64];

    const int tid = threadIdx.x;
    const int ty = tid >> 4;
    const int tx = tid & 15;
    const int qt = blockIdx.x;
    const int bh = blockIdx.y;

    const float* Qb = Q + (size_t)bh * TT * DKk;
    const float* Kb = K + (size_t)bh * TT * DKk;
    const float* Vb = V + (size_t)bh * TT * DKk;

#pragma unroll
    for (int it = 0; it < 4; it++) {
        int s = tid + it * 256;
        int r = s >> 4;
        int c = (s & 15) * 4;
        float4 v = *(const float4*)&Qb[(size_t)(qt * 64 + r) * DKk + c];
        Qs[r][c + 0] = v.x; Qs[r][c + 1] = v.y;
        Qs[r][c + 2] = v.z; Qs[r][c + 3] = v.w;
    }
    if (tid < 64) { row_m[tid] = -1e30f; row_l[tid] = 0.0f; }

    float accO[4][4];
#pragma unroll
    for (int i = 0; i < 4; i++)
#pragma unroll
        for (int j = 0; j < 4; j++) accO[i][j] = 0.0f;

    __syncthreads();

    const int nkt = 2 * qt + 2;
    for (int kt = 0; kt < nkt; kt++) {
#pragma unroll
        for (int it = 0; it < 2; it++) {
            int s = tid + it * 256;
            int r = s >> 4;
            int c = (s & 15) * 4;
            float4 kv = *(const float4*)&Kb[(size_t)(kt * 32 + r) * DKk + c];
            Ks[r][c + 0] = kv.x; Ks[r][c + 1] = kv.y;
            Ks[r][c + 2] = kv.z; Ks[r][c + 3] = kv.w;
            float4 vv = *(const float4*)&Vb[(size_t)(kt * 32 + r) * DKk + c];
            *(float4*)&Vs[r][c] = vv;
        }
        __syncthreads();

        float sacc[4][2];
#pragma unroll
        for (int i = 0; i < 4; i++) { sacc[i][0] = 0.0f; sacc[i][1] = 0.0f; }
#pragma unroll 8
        for (int k = 0; k < 64; k++) {
            float b0 = Ks[2 * tx + 0][k];
            float b1 = Ks[2 * tx + 1][k];
#pragma unroll
            for (int i = 0; i < 4; i++) {
                float a = Qs[4 * ty + i][k];
                sacc[i][0] = fmaf(a, b0, sacc[i][0]);
                sacc[i][1] = fmaf(a, b1, sacc[i][1]);
            }
        }
#pragma unroll
        for (int i = 0; i < 4; i++) {
            int qg = qt * 64 + 4 * ty + i;
#pragma unroll
            for (int j = 0; j < 2; j++) {
                int kg = kt * 32 + 2 * tx + j;
                Ss[4 * ty + i][2 * tx + j] = (kg <= qg) ? sacc[i][j] : -1e30f;
            }
        }
        __syncthreads();

        if (tid < 64) {
            int r = tid;
            float m_old = row_m[r];
            float m = m_old;
#pragma unroll 8
            for (int c = 0; c < 32; c++) m = fmaxf(m, Ss[r][c]);
            float alpha = __expf(m_old - m);
            float sum = 0.0f;
#pragma unroll 8
            for (int c = 0; c < 32; c++) {
                float p = __expf(Ss[r][c] - m);
                Ss[r][c] = p;
                sum += p;
            }
            row_m[r] = m;
            row_l[r] = row_l[r] * alpha + sum;
            row_alpha[r] = alpha;
        }
        __syncthreads();

        float al[4];
#pragma unroll
        for (int i = 0; i < 4; i++) al[i] = row_alpha[4 * ty + i];
#pragma unroll
        for (int i = 0; i < 4; i++)
#pragma unroll
            for (int j = 0; j < 4; j++) accO[i][j] *= al[i];
#pragma unroll 8
        for (int k = 0; k < 32; k++) {
            float4 bv = *(const float4*)&Vs[k][4 * tx];
            float b[4] = {bv.x, bv.y, bv.z, bv.w};
#pragma unroll
            for (int i = 0; i < 4; i++) {
                float a = Ss[4 * ty + i][k];
                accO[i][0] = fmaf(a, b[0], accO[i][0]);
                accO[i][1] = fmaf(a, b[1], accO[i][1]);
                accO[i][2] = fmaf(a, b[2], accO[i][2]);
                accO[i][3] = fmaf(a, b[3], accO[i][3]);
            }
        }
        __syncthreads();
    }

    const int b = bh >> 4;
    const int h = bh & 15;
#pragma unroll
    for (int i = 0; i < 4; i++) {
        int qg = qt * 64 + 4 * ty + i;
        float linv = 1.0f / row_l[4 * ty + i];
        float4 o;
        o.x = accO[i][0] * linv;
        o.y = accO[i][1] * linv;
        o.z = accO[i][2] * linv;
        o.w = accO[i][3] * linv;
        *(float4*)&out[((size_t)b * TT + qg) * DM + h * DKk + 4 * tx] = o;
    }
}

// ---------------------------------------------------------------------------
extern "C" void kernel_launch(void* const* d_in, const int* in_sizes, int n_in,
                              void* d_out, int out_size)
{
    const float* query = (const float*)d_in[0];
    const float* key   = (const float*)d_in[1];
    const float* value = (const float*)d_in[2];
    // d_in[3] = mask (causal tril, known statically — unused)
    const float* Wq = (const float*)d_in[4];
    const float* bq = (const float*)d_in[5];
    const float* Wk = (const float*)d_in[6];
    const float* bk = (const float*)d_in[7];
    const float* Wv = (const float*)d_in[8];
    const float* bv = (const float*)d_in[9];
    const float* Wo = (const float*)d_in[10];
    const float* bo = (const float*)d_in[11];
    float* out = (float*)d_out;

    float *q, *k, *v, *ao;
    cudaGetSymbolAddress((void**)&q,  g_q);
    cudaGetSymbolAddress((void**)&k,  g_k);
    cudaGetSymbolAddress((void**)&v,  g_v);
    cudaGetSymbolAddress((void**)&ao, g_ao);

    cudaFuncSetAttribute(gemm_tf32_kernel<1>,
                         cudaFuncAttributeMaxDynamicSharedMemorySize, GEMM_SMEM_BYTES);
    cudaFuncSetAttribute(gemm_tf32_kernel<0>,
                         cudaFuncAttributeMaxDynamicSharedMemorySize, GEMM_SMEM_BYTES);

    const int M = BB * TT;               // 8192
    dim3 gemm_grid(DM / 128, M / 128);   // (8, 64)

    // QKV projections on tensor cores (Q pre-scaled by 1/sqrt(Dk) = 0.125)
    gemm_tf32_kernel<1><<<gemm_grid, 256, GEMM_SMEM_BYTES>>>(query, Wq, bq, q, M, DM, DM, 0.125f);
    gemm_tf32_kernel<1><<<gemm_grid, 256, GEMM_SMEM_BYTES>>>(key,   Wk, bk, k, M, DM, DM, 1.0f);
    gemm_tf32_kernel<1><<<gemm_grid, 256, GEMM_SMEM_BYTES>>>(value, Wv, bv, v, M, DM, DM, 1.0f);

    // Flash attention (causal, fp32 this round)
    dim3 fa_grid(TT / 64, BB * HH);      // (32, 64)
    flash_attn_kernel<<<fa_grid, 256>>>(q, k, v, ao);

    // Output projection
    gemm_tf32_kernel<0><<<gemm_grid, 256, GEMM_SMEM_BYTES>>>(ao, Wo, bo, out, M, DM, DM, 1.0f);
}

// round 4
// speedup vs baseline: 3.0205x; 1.7948x over previous
#include <cuda_runtime.h>
#include <cstdint>

#define BB 4
#define TT 2048
#define HH 16
#define DKk 64
#define DM 1024

// Scratch (static device globals: allocation-free, graph-capture safe)
__device__ float g_q[BB * HH * TT * DKk];   // [B,H,T,Dk], tf32-rounded, scaled by 0.125*log2(e)
__device__ float g_k[BB * HH * TT * DKk];   // [B,H,T,Dk], tf32-rounded
__device__ float g_v[BB * HH * TT * DKk];   // [B,H,T,Dk], tf32-rounded
__device__ float g_ao[BB * TT * DM];        // [B,T,D] attention output (pre-Wo)

// ---------------------------------------------------------------------------
// Baseline-PTX helpers (harness ptxas targets plain sm_103: tcgen05 is
// unavailable; mma.sync + cp.async are fine and hit the tensor pipe)
// ---------------------------------------------------------------------------
__device__ __forceinline__ void cp_async16(uint32_t s, const void* g) {
    asm volatile("cp.async.cg.shared.global [%0], [%1], 16;\n" :: "r"(s), "l"(g));
}
__device__ __forceinline__ void cp_commit() {
    asm volatile("cp.async.commit_group;\n" ::: "memory");
}
__device__ __forceinline__ void cp_wait2() {
    asm volatile("cp.async.wait_group 2;\n" ::: "memory");
}
__device__ __forceinline__ void cp_wait1() {
    asm volatile("cp.async.wait_group 1;\n" ::: "memory");
}

__device__ __forceinline__ uint32_t f2tf32(float x) {
    uint32_t r;
    asm("cvt.rna.tf32.f32 %0, %1;" : "=r"(r) : "f"(x));
    return r;
}

// D += A(16x8 tf32, row) * B(8x8 tf32, col)
__device__ __forceinline__ void mma_tf32(float* c, const uint32_t* a, const uint32_t* b) {
    asm volatile(
        "mma.sync.aligned.m16n8k8.row.col.f32.tf32.tf32.f32 "
        "{%0,%1,%2,%3}, {%4,%5,%6,%7}, {%8,%9}, {%0,%1,%2,%3};"
        : "+f"(c[0]), "+f"(c[1]), "+f"(c[2]), "+f"(c[3])
        : "r"(a[0]), "r"(a[1]), "r"(a[2]), "r"(a[3]), "r"(b[0]), "r"(b[1]));
}

// ---------------------------------------------------------------------------
// Tensor-core tf32 GEMM: C = (X @ W^T + bias) * scale   (as round 3, proven)
// HEAD_LAYOUT=1: scatter to [B,H,T,Dk] AND round values to tf32 bit patterns
// so the attention kernel can feed smem data straight into mma without cvt.
// ---------------------------------------------------------------------------
#define SROW 36
#define STAGE_FLOATS (2 * 128 * SROW)
#define GEMM_SMEM_BYTES (4 * STAGE_FLOATS * 4)

template <int HEAD_LAYOUT>
__global__ __launch_bounds__(256)
void gemm_tf32_kernel(const float* __restrict__ X, const float* __restrict__ W,
                      const float* __restrict__ bias, float* __restrict__ out,
                      int M, int N, int K, float scale)
{
    extern __shared__ float smem[];
    const uint32_t smem_base = (uint32_t)__cvta_generic_to_shared(smem);
    const int tid = threadIdx.x;
    const int wid = tid >> 5;
    const int lane = tid & 31;
    const int g = lane >> 2;
    const int tig = lane & 3;
    const int wm = wid >> 2;
    const int wn = wid & 3;
    const int m0 = blockIdx.y * 128;
    const int n0 = blockIdx.x * 128;
    const int KT = K >> 5;

    auto load_tile = [&](int tile) {
        const int k0 = tile << 5;
        const uint32_t base = smem_base + (uint32_t)(tile & 3) * (STAGE_FLOATS * 4);
#pragma unroll
        for (int i = 0; i < 4; i++) {
            int idx = tid + (i << 8);
            int r = idx >> 3;
            int c = idx & 7;
            uint32_t dst = base + (uint32_t)(r * SROW * 4 + c * 16);
            cp_async16(dst, X + (size_t)(m0 + r) * K + k0 + c * 4);
            cp_async16(dst + 128 * SROW * 4, W + (size_t)(n0 + r) * K + k0 + c * 4);
        }
    };

#pragma unroll
    for (int t = 0; t < 3; t++) { load_tile(t); cp_commit(); }

    float acc[4][4][4];
#pragma unroll
    for (int fm = 0; fm < 4; fm++)
#pragma unroll
        for (int fn = 0; fn < 4; fn++)
#pragma unroll
            for (int e = 0; e < 4; e++) acc[fm][fn][e] = 0.0f;

    for (int kt = 0; kt < KT; kt++) {
        cp_wait2();
        __syncthreads();
        if (kt + 3 < KT) load_tile(kt + 3);
        cp_commit();

        const float* sA = smem + (size_t)(kt & 3) * STAGE_FLOATS;
        const float* sB = sA + 128 * SROW;

#pragma unroll
        for (int ks = 0; ks < 4; ks++) {
            const int kb = ks * 8;
            uint32_t a[4][4];
#pragma unroll
            for (int fm = 0; fm < 4; fm++) {
                const float* ar = sA + (wm * 64 + fm * 16 + g) * SROW + kb + tig;
                a[fm][0] = f2tf32(ar[0]);
                a[fm][1] = f2tf32(ar[8 * SROW]);
                a[fm][2] = f2tf32(ar[4]);
                a[fm][3] = f2tf32(ar[8 * SROW + 4]);
            }
            uint32_t b[4][2];
#pragma unroll
            for (int fn = 0; fn < 4; fn++) {
                const float* br = sB + (wn * 32 + fn * 8 + g) * SROW + kb + tig;
                b[fn][0] = f2tf32(br[0]);
                b[fn][1] = f2tf32(br[4]);
            }
#pragma unroll
            for (int fm = 0; fm < 4; fm++)
#pragma unroll
                for (int fn = 0; fn < 4; fn++)
                    mma_tf32(acc[fm][fn], a[fm], b[fn]);
        }
    }

#pragma unroll
    for (int fm = 0; fm < 4; fm++) {
#pragma unroll
        for (int fn = 0; fn < 4; fn++) {
            int n = n0 + wn * 32 + fn * 8 + 2 * tig;
            float bx = __ldg(&bias[n]);
            float by = __ldg(&bias[n + 1]);
#pragma unroll
            for (int half = 0; half < 2; half++) {
                int m = m0 + wm * 64 + fm * 16 + g + half * 8;
                float2 o;
                o.x = (acc[fm][fn][half * 2 + 0] + bx) * scale;
                o.y = (acc[fm][fn][half * 2 + 1] + by) * scale;
                if (HEAD_LAYOUT) {
                    // round to tf32 bit pattern for direct mma consumption
                    o.x = __uint_as_float(f2tf32(o.x));
                    o.y = __uint_as_float(f2tf32(o.y));
                    int b = m / TT, t = m % TT;
                    int h = n / DKk, dk = n % DKk;
                    *(float2*)&out[(((size_t)b * HH + h) * TT + t) * DKk + dk] = o;
                } else {
                    *(float2*)&out[(size_t)m * N + n] = o;
                }
            }
        }
    }
}

// ---------------------------------------------------------------------------
// Tensor-core flash attention (causal). Q pre-scaled by 0.125*log2(e); q/k/v
// already tf32-rounded by projection epilogue -> zero cvt in S and PV mma.
// BQ=128 q rows per CTA, BK=64 kv per tile, 8 warps x 16 q-rows.
// smem floats: Q[128][68] | K[2][64][68] | V[2][64][68] | P[128][68]
// ---------------------------------------------------------------------------
#define FSTR 68
#define OFF_K (128 * FSTR)
#define OFF_V (OFF_K + 2 * 64 * FSTR)
#define OFF_P (OFF_V + 2 * 64 * FSTR)
#define FA_SMEM_FLOATS (OFF_P + 128 * FSTR)
#define FA_SMEM_BYTES (FA_SMEM_FLOATS * 4)   // 139264

__global__ __launch_bounds__(256)
void flash_tc_kernel(const float* __restrict__ Q, const float* __restrict__ K,
                     const float* __restrict__ V, float* __restrict__ out)
{
    extern __shared__ float sm[];
    const uint32_t smb = (uint32_t)__cvta_generic_to_shared(sm);
    const int tid = threadIdx.x;
    const int wid = tid >> 5;
    const int lane = tid & 31;
    const int g = lane >> 2;
    const int tig = lane & 3;
    const int qt = blockIdx.x;
    const int bh = blockIdx.y;

    const float* Qb = Q + ((size_t)bh * TT + qt * 128) * DKk;
    const float* Kb = K + (size_t)bh * TT * DKk;
    const float* Vb = V + (size_t)bh * TT * DKk;

    // Load Q tile 128x64 (2048 float4, 8/thread)
#pragma unroll
    for (int i = 0; i < 8; i++) {
        int idx = tid + (i << 8);
        int r = idx >> 4;
        int c = idx & 15;
        cp_async16(smb + (uint32_t)((r * FSTR + c * 4) * 4), Qb + r * DKk + c * 4);
    }

    auto load_kv = [&](int kt) {
        const int buf = kt & 1;
        const float* kp = Kb + (size_t)kt * 64 * DKk;
        const float* vp = Vb + (size_t)kt * 64 * DKk;
        const uint32_t kb_ = smb + (uint32_t)((OFF_K + buf * 64 * FSTR) * 4);
        const uint32_t vb_ = smb + (uint32_t)((OFF_V + buf * 64 * FSTR) * 4);
#pragma unroll
        for (int i = 0; i < 4; i++) {
            int idx = tid + (i << 8);
            int r = idx >> 4;
            int c = idx & 15;
            uint32_t o = (uint32_t)((r * FSTR + c * 4) * 4);
            cp_async16(kb_ + o, kp + r * DKk + c * 4);
            cp_async16(vb_ + o, vp + r * DKk + c * 4);
        }
    };

    load_kv(0);
    cp_commit();   // group: {Q, KV0}

    float m0r = -1e30f, m1r = -1e30f, l0 = 0.0f, l1 = 0.0f;
    float o[8][4];
#pragma unroll
    for (int nf = 0; nf < 8; nf++)
#pragma unroll
        for (int e = 0; e < 4; e++) o[nf][e] = 0.0f;

    const int nkt = 2 * qt + 2;
    const int row0 = wid * 16 + g;           // local q row (and +8)
    const uint32_t* Qw = (const uint32_t*)sm + row0 * FSTR;
    uint32_t* Pw = (uint32_t*)(sm + OFF_P) + row0 * FSTR;

    for (int kt = 0; kt < nkt; kt++) {
        __syncthreads();                      // prev tile fully consumed
        if (kt + 1 < nkt) load_kv(kt + 1);
        cp_commit();
        cp_wait1();                           // tile kt resident
        __syncthreads();

        const int buf = kt & 1;
        const uint32_t* Ks = (const uint32_t*)(sm + OFF_K + buf * 64 * FSTR);
        const float* Vs = sm + OFF_V + buf * 64 * FSTR;

        // ---- S = Q @ K^T (128x64 per CTA, 16x64 per warp) ----
        float s[8][4];
#pragma unroll
        for (int nf = 0; nf < 8; nf++)
#pragma unroll
            for (int e = 0; e < 4; e++) s[nf][e] = 0.0f;

#pragma unroll
        for (int ks = 0; ks < 8; ks++) {
            const int kb = ks * 8;
            uint32_t a[4];
            a[0] = Qw[kb + tig];
            a[1] = Qw[8 * FSTR + kb + tig];
            a[2] = Qw[kb + tig + 4];
            a[3] = Qw[8 * FSTR + kb + tig + 4];
#pragma unroll
            for (int nf = 0; nf < 8; nf++) {
                uint32_t b[2];
                const uint32_t* kr = Ks + (nf * 8 + g) * FSTR + kb + tig;
                b[0] = kr[0];
                b[1] = kr[4];
                mma_tf32(s[nf], a, b);
            }
        }

        // ---- causal mask (only the last two tiles straddle the diagonal) ----
        if (kt >= 2 * qt) {
            const int qg0 = qt * 128 + row0;
            const int qg1 = qg0 + 8;
#pragma unroll
            for (int nf = 0; nf < 8; nf++) {
                int kg = kt * 64 + nf * 8 + 2 * tig;
                if (kg > qg0) s[nf][0] = -1e30f;
                if (kg + 1 > qg0) s[nf][1] = -1e30f;
                if (kg > qg1) s[nf][2] = -1e30f;
                if (kg + 1 > qg1) s[nf][3] = -1e30f;
            }
        }

        // ---- online softmax (base-2; Q carries the log2e*scale factor) ----
        float mx0 = -1e30f, mx1 = -1e30f;
#pragma unroll
        for (int nf = 0; nf < 8; nf++) {
            mx0 = fmaxf(mx0, fmaxf(s[nf][0], s[nf][1]));
            mx1 = fmaxf(mx1, fmaxf(s[nf][2], s[nf][3]));
        }
        mx0 = fmaxf(mx0, __shfl_xor_sync(0xffffffffu, mx0, 1));
        mx0 = fmaxf(mx0, __shfl_xor_sync(0xffffffffu, mx0, 2));
        mx1 = fmaxf(mx1, __shfl_xor_sync(0xffffffffu, mx1, 1));
        mx1 = fmaxf(mx1, __shfl_xor_sync(0xffffffffu, mx1, 2));

        float mn0 = fmaxf(m0r, mx0);
        float mn1 = fmaxf(m1r, mx1);
        float al0 = exp2f(m0r - mn0);
        float al1 = exp2f(m1r - mn1);
        m0r = mn0; m1r = mn1;

        float sum0 = 0.0f, sum1 = 0.0f;
#pragma unroll
        for (int nf = 0; nf < 8; nf++) {
            s[nf][0] = exp2f(s[nf][0] - mn0); sum0 += s[nf][0];
            s[nf][1] = exp2f(s[nf][1] - mn0); sum0 += s[nf][1];
            s[nf][2] = exp2f(s[nf][2] - mn1); sum1 += s[nf][2];
            s[nf][3] = exp2f(s[nf][3] - mn1); sum1 += s[nf][3];
        }
        sum0 += __shfl_xor_sync(0xffffffffu, sum0, 1);
        sum0 += __shfl_xor_sync(0xffffffffu, sum0, 2);
        sum1 += __shfl_xor_sync(0xffffffffu, sum1, 1);
        sum1 += __shfl_xor_sync(0xffffffffu, sum1, 2);
        l0 = l0 * al0 + sum0;
        l1 = l1 * al1 + sum1;

        // rescale O
#pragma unroll
        for (int nf = 0; nf < 8; nf++) {
            o[nf][0] *= al0; o[nf][1] *= al0;
            o[nf][2] *= al1; o[nf][3] *= al1;
        }

        // ---- store P (tf32-rounded) to warp-private smem region ----
#pragma unroll
        for (int nf = 0; nf < 8; nf++) {
            int c = nf * 8 + 2 * tig;
            Pw[c] = f2tf32(s[nf][0]);
            Pw[c + 1] = f2tf32(s[nf][1]);
            Pw[8 * FSTR + c] = f2tf32(s[nf][2]);
            Pw[8 * FSTR + c + 1] = f2tf32(s[nf][3]);
        }
        __syncwarp();

        // ---- O += P @ V ----
#pragma unroll
        for (int ks = 0; ks < 8; ks++) {
            const int kb = ks * 8;
            uint32_t a[4];
            a[0] = Pw[kb + tig];
            a[1] = Pw[8 * FSTR + kb + tig];
            a[2] = Pw[kb + tig + 4];
            a[3] = Pw[8 * FSTR + kb + tig + 4];
            const uint32_t* vr = (const uint32_t*)(Vs + (kb + tig) * FSTR + g);
#pragma unroll
            for (int nf = 0; nf < 8; nf++) {
                uint32_t b[2];
                b[0] = vr[nf * 8];
                b[1] = vr[4 * FSTR + nf * 8];
                mma_tf32(o[nf], a, b);
            }
        }
    }

    // ---- epilogue: O /= l, write [B,T,D] ----
    const int b = bh >> 4;
    const int h = bh & 15;
    const float li0 = 1.0f / l0;
    const float li1 = 1.0f / l1;
    const int qg0 = qt * 128 + row0;
#pragma unroll
    for (int nf = 0; nf < 8; nf++) {
        int col = h * DKk + nf * 8 + 2 * tig;
        float2 o0 = make_float2(o[nf][0] * li0, o[nf][1] * li0);
        float2 o1 = make_float2(o[nf][2] * li1, o[nf][3] * li1);
        *(float2*)&out[((size_t)b * TT + qg0) * DM + col] = o0;
        *(float2*)&out[((size_t)b * TT + qg0 + 8) * DM + col] = o1;
    }
}

// ---------------------------------------------------------------------------
extern "C" void kernel_launch(void* const* d_in, const int* in_sizes, int n_in,
                              void* d_out, int out_size)
{
    const float* query = (const float*)d_in[0];
    const float* key   = (const float*)d_in[1];
    const float* value = (const float*)d_in[2];
    // d_in[3] = mask (causal tril, known statically — unused)
    const float* Wq = (const float*)d_in[4];
    const float* bq = (const float*)d_in[5];
    const float* Wk = (const float*)d_in[6];
    const float* bk = (const float*)d_in[7];
    const float* Wv = (const float*)d_in[8];
    const float* bv = (const float*)d_in[9];
    const float* Wo = (const float*)d_in[10];
    const float* bo = (const float*)d_in[11];
    float* out = (float*)d_out;

    float *q, *k, *v, *ao;
    cudaGetSymbolAddress((void**)&q,  g_q);
    cudaGetSymbolAddress((void**)&k,  g_k);
    cudaGetSymbolAddress((void**)&v,  g_v);
    cudaGetSymbolAddress((void**)&ao, g_ao);

    cudaFuncSetAttribute(gemm_tf32_kernel<1>,
                         cudaFuncAttributeMaxDynamicSharedMemorySize, GEMM_SMEM_BYTES);
    cudaFuncSetAttribute(gemm_tf32_kernel<0>,
                         cudaFuncAttributeMaxDynamicSharedMemorySize, GEMM_SMEM_BYTES);
    cudaFuncSetAttribute(flash_tc_kernel,
                         cudaFuncAttributeMaxDynamicSharedMemorySize, FA_SMEM_BYTES);

    const int M = BB * TT;               // 8192
    dim3 gemm_grid(DM / 128, M / 128);   // (8, 64)

    // QKV projections (Q folds softmax scale AND log2(e) for exp2-domain softmax)
    const float qscale = 0.125f * 1.4426950408889634f;
    gemm_tf32_kernel<1><<<gemm_grid, 256, GEMM_SMEM_BYTES>>>(query, Wq, bq, q, M, DM, DM, qscale);
    gemm_tf32_kernel<1><<<gemm_grid, 256, GEMM_SMEM_BYTES>>>(key,   Wk, bk, k, M, DM, DM, 1.0f);
    gemm_tf32_kernel<1><<<gemm_grid, 256, GEMM_SMEM_BYTES>>>(value, Wv, bv, v, M, DM, DM, 1.0f);

    // Tensor-core flash attention (causal)
    dim3 fa_grid(TT / 128, BB * HH);     // (16, 64)
    flash_tc_kernel<<<fa_grid, 256, FA_SMEM_BYTES>>>(q, k, v, ao);

    // Output projection
    gemm_tf32_kernel<0><<<gemm_grid, 256, GEMM_SMEM_BYTES>>>(ao, Wo, bo, out, M, DM, DM, 1.0f);
}

// round 5
// speedup vs baseline: 3.5782x; 1.1847x over previous
#include <cuda_runtime.h>
#include <cstdint>

#define BB 4
#define TT 2048
#define HH 16
#define DKk 64
#define DM 1024

// Scratch (static device globals: allocation-free, graph-capture safe)
__device__ float g_q[BB * HH * TT * DKk];   // [B,H,T,Dk], tf32-rounded, scaled
__device__ float g_k[BB * HH * TT * DKk];
__device__ float g_v[BB * HH * TT * DKk];
__device__ float g_ao[BB * TT * DM];        // [B,T,D], tf32-rounded by flash epilogue
// tf32-rounded copies of GEMM inputs (removes cvt from GEMM inner loops)
__device__ float g_xq[BB * TT * DM];
__device__ float g_xk[BB * TT * DM];
__device__ float g_xv[BB * TT * DM];
__device__ float g_wq[DM * DM];
__device__ float g_wk[DM * DM];
__device__ float g_wv[DM * DM];
__device__ float g_wo[DM * DM];

// ---------------------------------------------------------------------------
// Baseline-PTX helpers (harness ptxas targets plain sm_103: no tcgen05;
// mma.sync + cp.async compile and hit the tensor pipe)
// ---------------------------------------------------------------------------
__device__ __forceinline__ void cp_async16(uint32_t s, const void* g) {
    asm volatile("cp.async.cg.shared.global [%0], [%1], 16;\n" :: "r"(s), "l"(g));
}
__device__ __forceinline__ void cp_commit() {
    asm volatile("cp.async.commit_group;\n" ::: "memory");
}
__device__ __forceinline__ void cp_wait1() {
    asm volatile("cp.async.wait_group 1;\n" ::: "memory");
}

__device__ __forceinline__ uint32_t f2tf32(float x) {
    uint32_t r;
    asm("cvt.rna.tf32.f32 %0, %1;" : "=r"(r) : "f"(x));
    return r;
}

// D += A(16x8 tf32, row) * B(8x8 tf32, col)
__device__ __forceinline__ void mma_tf32(float* c, const uint32_t* a, const uint32_t* b) {
    asm volatile(
        "mma.sync.aligned.m16n8k8.row.col.f32.tf32.tf32.f32 "
        "{%0,%1,%2,%3}, {%4,%5,%6,%7}, {%8,%9}, {%0,%1,%2,%3};"
        : "+f"(c[0]), "+f"(c[1]), "+f"(c[2]), "+f"(c[3])
        : "r"(a[0]), "r"(a[1]), "r"(a[2]), "r"(a[3]), "r"(b[0]), "r"(b[1]));
}

// ---------------------------------------------------------------------------
// tf32 rounding pre-pass (grid-stride float4)
// ---------------------------------------------------------------------------
__global__ __launch_bounds__(256)
void round_tf32_kernel(const float4* __restrict__ in, float4* __restrict__ out, int n4)
{
    int i = blockIdx.x * blockDim.x + threadIdx.x;
    int stride = gridDim.x * blockDim.x;
    for (; i < n4; i += stride) {
        float4 v = in[i];
        v.x = __uint_as_float(f2tf32(v.x));
        v.y = __uint_as_float(f2tf32(v.y));
        v.z = __uint_as_float(f2tf32(v.z));
        v.w = __uint_as_float(f2tf32(v.w));
        out[i] = v;
    }
}

// ---------------------------------------------------------------------------
// Tensor-core tf32 GEMM: C = (X @ W^T + bias) * scale
// Inputs PRE-ROUNDED to tf32 -> inner loop is pure LDS + MMA (no cvt).
// CTA tile 128x128, BK=32, 3-stage cp.async pipeline (1 sync/ktile), 8 warps,
// warp tile 64x32. 2 CTAs/SM (110.6 KB smem, <=128 regs).
// ---------------------------------------------------------------------------
#define SROW 36
#define STAGE_FLOATS (2 * 128 * SROW)
#define GEMM_SMEM_BYTES (3 * STAGE_FLOATS * 4)     // 110592

template <int HEAD_LAYOUT>
__global__ __launch_bounds__(256, 2)
void gemm_tf32_kernel(const float* __restrict__ X, const float* __restrict__ W,
                      const float* __restrict__ bias, float* __restrict__ out,
                      int M, int N, int K, float scale)
{
    extern __shared__ float smem[];
    const uint32_t smem_base = (uint32_t)__cvta_generic_to_shared(smem);
    const int tid = threadIdx.x;
    const int wid = tid >> 5;
    const int lane = tid & 31;
    const int g = lane >> 2;
    const int tig = lane & 3;
    const int wm = wid >> 2;
    const int wn = wid & 3;
    const int m0 = blockIdx.y * 128;
    const int n0 = blockIdx.x * 128;
    const int KT = K >> 5;

    auto load_tile = [&](int tile) {
        const int k0 = tile << 5;
        const uint32_t base = smem_base + (uint32_t)(tile % 3) * (STAGE_FLOATS * 4);
#pragma unroll
        for (int i = 0; i < 4; i++) {
            int idx = tid + (i << 8);
            int r = idx >> 3;
            int c = idx & 7;
            uint32_t dst = base + (uint32_t)(r * SROW * 4 + c * 16);
            cp_async16(dst, X + (size_t)(m0 + r) * K + k0 + c * 4);
            cp_async16(dst + 128 * SROW * 4, W + (size_t)(n0 + r) * K + k0 + c * 4);
        }
    };

    load_tile(0); cp_commit();
    load_tile(1); cp_commit();

    float acc[4][4][4];
#pragma unroll
    for (int fm = 0; fm < 4; fm++)
#pragma unroll
        for (int fn = 0; fn < 4; fn++)
#pragma unroll
            for (int e = 0; e < 4; e++) acc[fm][fn][e] = 0.0f;

    for (int kt = 0; kt < KT; kt++) {
        cp_wait1();                 // tile kt resident (kt+1 may be pending)
        __syncthreads();            // all warps done with tile kt-1 (slot (kt+2)%3)
        if (kt + 2 < KT) load_tile(kt + 2);
        cp_commit();

        const uint32_t* sA = (const uint32_t*)smem + (size_t)(kt % 3) * STAGE_FLOATS;
        const uint32_t* sB = sA + 128 * SROW;

#pragma unroll
        for (int ks = 0; ks < 4; ks++) {
            const int kb = ks * 8;
            uint32_t a[4][4];
#pragma unroll
            for (int fm = 0; fm < 4; fm++) {
                const uint32_t* ar = sA + (wm * 64 + fm * 16 + g) * SROW + kb + tig;
                a[fm][0] = ar[0];
                a[fm][1] = ar[8 * SROW];
                a[fm][2] = ar[4];
                a[fm][3] = ar[8 * SROW + 4];
            }
            uint32_t b[4][2];
#pragma unroll
            for (int fn = 0; fn < 4; fn++) {
                const uint32_t* br = sB + (wn * 32 + fn * 8 + g) * SROW + kb + tig;
                b[fn][0] = br[0];
                b[fn][1] = br[4];
            }
#pragma unroll
            for (int fm = 0; fm < 4; fm++)
#pragma unroll
                for (int fn = 0; fn < 4; fn++)
                    mma_tf32(acc[fm][fn], a[fm], b[fn]);
        }
    }

#pragma unroll
    for (int fm = 0; fm < 4; fm++) {
#pragma unroll
        for (int fn = 0; fn < 4; fn++) {
            int n = n0 + wn * 32 + fn * 8 + 2 * tig;
            float bx = __ldg(&bias[n]);
            float by = __ldg(&bias[n + 1]);
#pragma unroll
            for (int half = 0; half < 2; half++) {
                int m = m0 + wm * 64 + fm * 16 + g + half * 8;
                float2 o;
                o.x = (acc[fm][fn][half * 2 + 0] + bx) * scale;
                o.y = (acc[fm][fn][half * 2 + 1] + by) * scale;
                if (HEAD_LAYOUT) {
                    o.x = __uint_as_float(f2tf32(o.x));   // pre-round for flash mma
                    o.y = __uint_as_float(f2tf32(o.y));
                    int b = m / TT, t = m % TT;
                    int h = n / DKk, dk = n % DKk;
                    *(float2*)&out[(((size_t)b * HH + h) * TT + t) * DKk + dk] = o;
                } else {
                    *(float2*)&out[(size_t)m * N + n] = o;
                }
            }
        }
    }
}

// ---------------------------------------------------------------------------
// Tensor-core flash attention (causal). Q pre-scaled by 0.125*log2(e); q/k/v
// tf32-rounded -> zero cvt in S and PV mma (P keeps 32 cvt/tile).
// BQ=128, BK=32, triple-buffered KV, ONE __syncthreads per tile.
// smem floats: Q[128][68] | K[3][32][68] | V[3][32][72] | P[128][36]
// = 104.5 KB -> 2 CTAs/SM.
// ---------------------------------------------------------------------------
#define QSTR 68
#define KSTR 68
#define VSTR 72
#define PSTR 36
#define OFF_K (128 * QSTR)
#define OFF_V (OFF_K + 3 * 32 * KSTR)
#define OFF_P (OFF_V + 3 * 32 * VSTR)
#define FA_SMEM_FLOATS (OFF_P + 128 * PSTR)
#define FA_SMEM_BYTES (FA_SMEM_FLOATS * 4)   // 107008

__global__ __launch_bounds__(256, 2)
void flash_tc_kernel(const float* __restrict__ Q, const float* __restrict__ K,
                     const float* __restrict__ V, float* __restrict__ out)
{
    extern __shared__ float sm[];
    const uint32_t smb = (uint32_t)__cvta_generic_to_shared(sm);
    const int tid = threadIdx.x;
    const int wid = tid >> 5;
    const int lane = tid & 31;
    const int g = lane >> 2;
    const int tig = lane & 3;
    const int qt = blockIdx.x;
    const int bh = blockIdx.y;

    const float* Qb = Q + ((size_t)bh * TT + qt * 128) * DKk;
    const float* Kb = K + (size_t)bh * TT * DKk;
    const float* Vb = V + (size_t)bh * TT * DKk;

    // Load Q tile 128x64 (2048 float4, 8/thread)
#pragma unroll
    for (int i = 0; i < 8; i++) {
        int idx = tid + (i << 8);
        int r = idx >> 4;
        int c = idx & 15;
        cp_async16(smb + (uint32_t)((r * QSTR + c * 4) * 4), Qb + r * DKk + c * 4);
    }

    auto load_kv = [&](int kt) {
        const int buf = kt % 3;
        const float* kp = Kb + (size_t)kt * 32 * DKk;
        const float* vp = Vb + (size_t)kt * 32 * DKk;
        const uint32_t kb_ = smb + (uint32_t)((OFF_K + buf * 32 * KSTR) * 4);
        const uint32_t vb_ = smb + (uint32_t)((OFF_V + buf * 32 * VSTR) * 4);
#pragma unroll
        for (int i = 0; i < 2; i++) {
            int idx = tid + (i << 8);      // 0..511
            int r = idx >> 4;              // 0..31
            int c = idx & 15;
            cp_async16(kb_ + (uint32_t)((r * KSTR + c * 4) * 4), kp + r * DKk + c * 4);
            cp_async16(vb_ + (uint32_t)((r * VSTR + c * 4) * 4), vp + r * DKk + c * 4);
        }
    };

    load_kv(0);
    cp_commit();       // G0 = {Q, KV0}
    load_kv(1);
    cp_commit();       // G1 = {KV1}

    float m0r = -1e30f, m1r = -1e30f, l0 = 0.0f, l1 = 0.0f;
    float o[8][4];
#pragma unroll
    for (int nf = 0; nf < 8; nf++)
#pragma unroll
        for (int e = 0; e < 4; e++) o[nf][e] = 0.0f;

    const int nkt = 4 * qt + 4;
    const int row0 = wid * 16 + g;
    const uint32_t* Qw = (const uint32_t*)sm + row0 * QSTR;
    uint32_t* Pw = (uint32_t*)(sm + OFF_P) + row0 * PSTR;

    for (int kt = 0; kt < nkt; kt++) {
        cp_wait1();                           // tile kt resident (kt+1 pending)
        __syncthreads();                      // tile kt-1 consumed by all warps
        if (kt + 2 < nkt) load_kv(kt + 2);    // overwrites slot (kt+2)%3 — safe
        cp_commit();

        const int buf = kt % 3;
        const uint32_t* Ks = (const uint32_t*)(sm + OFF_K + buf * 32 * KSTR);
        const uint32_t* Vs = (const uint32_t*)(sm + OFF_V + buf * 32 * VSTR);

        // ---- S = Q @ K^T (16x32 per warp) ----
        float s[4][4];
#pragma unroll
        for (int nf = 0; nf < 4; nf++)
#pragma unroll
            for (int e = 0; e < 4; e++) s[nf][e] = 0.0f;

#pragma unroll
        for (int ks = 0; ks < 8; ks++) {
            const int kb = ks * 8;
            uint32_t a[4];
            a[0] = Qw[kb + tig];
            a[1] = Qw[8 * QSTR + kb + tig];
            a[2] = Qw[kb + tig + 4];
            a[3] = Qw[8 * QSTR + kb + tig + 4];
#pragma unroll
            for (int nf = 0; nf < 4; nf++) {
                uint32_t b[2];
                const uint32_t* kr = Ks + (nf * 8 + g) * KSTR + kb + tig;
                b[0] = kr[0];
                b[1] = kr[4];
                mma_tf32(s[nf], a, b);
            }
        }

        // ---- causal mask (tiles kt >= 4*qt straddle/exceed the diagonal) ----
        if (kt >= 4 * qt) {
            const int qg0 = qt * 128 + row0;
            const int qg1 = qg0 + 8;
#pragma unroll
            for (int nf = 0; nf < 4; nf++) {
                int kg = kt * 32 + nf * 8 + 2 * tig;
                if (kg > qg0) s[nf][0] = -1e30f;
                if (kg + 1 > qg0) s[nf][1] = -1e30f;
                if (kg > qg1) s[nf][2] = -1e30f;
                if (kg + 1 > qg1) s[nf][3] = -1e30f;
            }
        }

        // ---- online softmax (base-2) ----
        float mx0 = -1e30f, mx1 = -1e30f;
#pragma unroll
        for (int nf = 0; nf < 4; nf++) {
            mx0 = fmaxf(mx0, fmaxf(s[nf][0], s[nf][1]));
            mx1 = fmaxf(mx1, fmaxf(s[nf][2], s[nf][3]));
        }
        mx0 = fmaxf(mx0, __shfl_xor_sync(0xffffffffu, mx0, 1));
        mx0 = fmaxf(mx0, __shfl_xor_sync(0xffffffffu, mx0, 2));
        mx1 = fmaxf(mx1, __shfl_xor_sync(0xffffffffu, mx1, 1));
        mx1 = fmaxf(mx1, __shfl_xor_sync(0xffffffffu, mx1, 2));

        float mn0 = fmaxf(m0r, mx0);
        float mn1 = fmaxf(m1r, mx1);
        float al0 = exp2f(m0r - mn0);
        float al1 = exp2f(m1r - mn1);
        m0r = mn0; m1r = mn1;

        float sum0 = 0.0f, sum1 = 0.0f;
#pragma unroll
        for (int nf = 0; nf < 4; nf++) {
            s[nf][0] = exp2f(s[nf][0] - mn0); sum0 += s[nf][0];
            s[nf][1] = exp2f(s[nf][1] - mn0); sum0 += s[nf][1];
            s[nf][2] = exp2f(s[nf][2] - mn1); sum1 += s[nf][2];
            s[nf][3] = exp2f(s[nf][3] - mn1); sum1 += s[nf][3];
        }
        sum0 += __shfl_xor_sync(0xffffffffu, sum0, 1);
        sum0 += __shfl_xor_sync(0xffffffffu, sum0, 2);
        sum1 += __shfl_xor_sync(0xffffffffu, sum1, 1);
        sum1 += __shfl_xor_sync(0xffffffffu, sum1, 2);
        l0 = l0 * al0 + sum0;
        l1 = l1 * al1 + sum1;

#pragma unroll
        for (int nf = 0; nf < 8; nf++) {
            o[nf][0] *= al0; o[nf][1] *= al0;
            o[nf][2] *= al1; o[nf][3] *= al1;
        }

        // ---- store P (tf32-rounded) to warp-private smem ----
#pragma unroll
        for (int nf = 0; nf < 4; nf++) {
            int c = nf * 8 + 2 * tig;
            Pw[c] = f2tf32(s[nf][0]);
            Pw[c + 1] = f2tf32(s[nf][1]);
            Pw[8 * PSTR + c] = f2tf32(s[nf][2]);
            Pw[8 * PSTR + c + 1] = f2tf32(s[nf][3]);
        }
        __syncwarp();

        // ---- O += P @ V (16x64 per warp) ----
#pragma unroll
        for (int ks = 0; ks < 4; ks++) {
            const int kb = ks * 8;
            uint32_t a[4];
            a[0] = Pw[kb + tig];
            a[1] = Pw[8 * PSTR + kb + tig];
            a[2] = Pw[kb + tig + 4];
            a[3] = Pw[8 * PSTR + kb + tig + 4];
            const uint32_t* vr = Vs + (kb + tig) * VSTR + g;
#pragma unroll
            for (int nf = 0; nf < 8; nf++) {
                uint32_t b[2];
                b[0] = vr[nf * 8];
                b[1] = vr[4 * VSTR + nf * 8];
                mma_tf32(o[nf], a, b);
            }
        }
    }

    // ---- epilogue: O /= l, tf32-round (for cvt-free final GEMM), write ----
    const int b = bh >> 4;
    const int h = bh & 15;
    const float li0 = 1.0f / l0;
    const float li1 = 1.0f / l1;
    const int qg0 = qt * 128 + row0;
#pragma unroll
    for (int nf = 0; nf < 8; nf++) {
        int col = h * DKk + nf * 8 + 2 * tig;
        float2 o0, o1;
        o0.x = __uint_as_float(f2tf32(o[nf][0] * li0));
        o0.y = __uint_as_float(f2tf32(o[nf][1] * li0));
        o1.x = __uint_as_float(f2tf32(o[nf][2] * li1));
        o1.y = __uint_as_float(f2tf32(o[nf][3] * li1));
        *(float2*)&out[((size_t)b * TT + qg0) * DM + col] = o0;
        *(float2*)&out[((size_t)b * TT + qg0 + 8) * DM + col] = o1;
    }
}

// ---------------------------------------------------------------------------
extern "C" void kernel_launch(void* const* d_in, const int* in_sizes, int n_in,
                              void* d_out, int out_size)
{
    const float* query = (const float*)d_in[0];
    const float* key   = (const float*)d_in[1];
    const float* value = (const float*)d_in[2];
    // d_in[3] = mask (causal tril, known statically — unused)
    const float* Wq = (const float*)d_in[4];
    const float* bq = (const float*)d_in[5];
    const float* Wk = (const float*)d_in[6];
    const float* bk = (const float*)d_in[7];
    const float* Wv = (const float*)d_in[8];
    const float* bv = (const float*)d_in[9];
    const float* Wo = (const float*)d_in[10];
    const float* bo = (const float*)d_in[11];
    float* out = (float*)d_out;

    float *q, *k, *v, *ao, *xq, *xk, *xv, *wq, *wk, *wv, *wo;
    cudaGetSymbolAddress((void**)&q,  g_q);
    cudaGetSymbolAddress((void**)&k,  g_k);
    cudaGetSymbolAddress((void**)&v,  g_v);
    cudaGetSymbolAddress((void**)&ao, g_ao);
    cudaGetSymbolAddress((void**)&xq, g_xq);
    cudaGetSymbolAddress((void**)&xk, g_xk);
    cudaGetSymbolAddress((void**)&xv, g_xv);
    cudaGetSymbolAddress((void**)&wq, g_wq);
    cudaGetSymbolAddress((void**)&wk, g_wk);
    cudaGetSymbolAddress((void**)&wv, g_wv);
    cudaGetSymbolAddress((void**)&wo, g_wo);

    cudaFuncSetAttribute(gemm_tf32_kernel<1>,
                         cudaFuncAttributeMaxDynamicSharedMemorySize, GEMM_SMEM_BYTES);
    cudaFuncSetAttribute(gemm_tf32_kernel<0>,
                         cudaFuncAttributeMaxDynamicSharedMemorySize, GEMM_SMEM_BYTES);
    cudaFuncSetAttribute(flash_tc_kernel,
                         cudaFuncAttributeMaxDynamicSharedMemorySize, FA_SMEM_BYTES);

    const int M = BB * TT;               // 8192
    const int NX4 = M * DM / 4;          // 2M float4
    const int NW4 = DM * DM / 4;         // 256K float4

    // tf32 pre-rounding passes (makes all GEMM inner loops cvt-free)
    round_tf32_kernel<<<592, 256>>>((const float4*)query, (float4*)xq, NX4);
    round_tf32_kernel<<<592, 256>>>((const float4*)key,   (float4*)xk, NX4);
    round_tf32_kernel<<<592, 256>>>((const float4*)value, (float4*)xv, NX4);
    round_tf32_kernel<<<592, 256>>>((const float4*)Wq, (float4*)wq, NW4);
    round_tf32_kernel<<<592, 256>>>((const float4*)Wk, (float4*)wk, NW4);
    round_tf32_kernel<<<592, 256>>>((const float4*)Wv, (float4*)wv, NW4);
    round_tf32_kernel<<<592, 256>>>((const float4*)Wo, (float4*)wo, NW4);

    dim3 gemm_grid(DM / 128, M / 128);   // (8, 64)

    // QKV projections (Q folds softmax scale AND log2(e) for exp2-domain softmax)
    const float qscale = 0.125f * 1.4426950408889634f;
    gemm_tf32_kernel<1><<<gemm_grid, 256, GEMM_SMEM_BYTES>>>(xq, wq, bq, q, M, DM, DM, qscale);
    gemm_tf32_kernel<1><<<gemm_grid, 256, GEMM_SMEM_BYTES>>>(xk, wk, bk, k, M, DM, DM, 1.0f);
    gemm_tf32_kernel<1><<<gemm_grid, 256, GEMM_SMEM_BYTES>>>(xv, wv, bv, v, M, DM, DM, 1.0f);

    // Tensor-core flash attention (causal)
    dim3 fa_grid(TT / 128, BB * HH);     // (16, 64)
    flash_tc_kernel<<<fa_grid, 256, FA_SMEM_BYTES>>>(q, k, v, ao);

    // Output projection (ao already tf32-rounded by flash epilogue)
    gemm_tf32_kernel<0><<<gemm_grid, 256, GEMM_SMEM_BYTES>>>(ao, wo, bo, out, M, DM, DM, 1.0f);
}

// round 6
// speedup vs baseline: 4.0897x; 1.1429x over previous
#include <cuda_runtime.h>
#include <cstdint>

#define BB 4
#define TT 2048
#define HH 16
#define DKk 64
#define DM 1024

// Scratch (static device globals: allocation-free, graph-capture safe)
__device__ float g_q[BB * HH * TT * DKk];   // [B,H,T,Dk], tf32-rounded, scaled
__device__ float g_k[BB * HH * TT * DKk];
__device__ float g_v[BB * HH * TT * DKk];
__device__ float g_ao[BB * TT * DM];        // [B,T,D], tf32-rounded by flash epilogue
// tf32-rounded copies of GEMM inputs (removes cvt from GEMM inner loops)
__device__ float g_xq[BB * TT * DM];
__device__ float g_xk[BB * TT * DM];
__device__ float g_xv[BB * TT * DM];
__device__ float g_wq[DM * DM];
__device__ float g_wk[DM * DM];
__device__ float g_wv[DM * DM];
__device__ float g_wo[DM * DM];

// ---------------------------------------------------------------------------
// Baseline-PTX helpers (harness ptxas targets plain sm_103: no tcgen05;
// mma.sync + cp.async + ldmatrix compile and hit the tensor pipe)
// ---------------------------------------------------------------------------
__device__ __forceinline__ void cp_async16(uint32_t s, const void* g) {
    asm volatile("cp.async.cg.shared.global [%0], [%1], 16;\n" :: "r"(s), "l"(g));
}
__device__ __forceinline__ void cp_commit() {
    asm volatile("cp.async.commit_group;\n" ::: "memory");
}
__device__ __forceinline__ void cp_wait1() {
    asm volatile("cp.async.wait_group 1;\n" ::: "memory");
}

__device__ __forceinline__ uint32_t f2tf32(float x) {
    uint32_t r;
    asm("cvt.rna.tf32.f32 %0, %1;" : "=r"(r) : "f"(x));
    return r;
}

// 4x (8 rows x 16B) shared-memory matrix load; for 32-bit data each matrix is
// an 8x4-float tile: lane i receives element (row i/4, col i%4) of matrix (lane/8 group).
__device__ __forceinline__ void ldmat_x4(uint32_t* r, uint32_t addr) {
    asm volatile("ldmatrix.sync.aligned.m8n8.x4.shared.b16 {%0,%1,%2,%3}, [%4];"
                 : "=r"(r[0]), "=r"(r[1]), "=r"(r[2]), "=r"(r[3]) : "r"(addr));
}

// D += A(16x8 tf32, row) * B(8x8 tf32, col)
__device__ __forceinline__ void mma_tf32(float* c, const uint32_t* a, const uint32_t* b) {
    asm volatile(
        "mma.sync.aligned.m16n8k8.row.col.f32.tf32.tf32.f32 "
        "{%0,%1,%2,%3}, {%4,%5,%6,%7}, {%8,%9}, {%0,%1,%2,%3};"
        : "+f"(c[0]), "+f"(c[1]), "+f"(c[2]), "+f"(c[3])
        : "r"(a[0]), "r"(a[1]), "r"(a[2]), "r"(a[3]), "r"(b[0]), "r"(b[1]));
}

// ---------------------------------------------------------------------------
// tf32 rounding pre-pass: two arrays per launch (blockIdx.y selects)
// ---------------------------------------------------------------------------
__global__ __launch_bounds__(256)
void round2_kernel(const float4* __restrict__ in0, float4* __restrict__ out0, int n0,
                   const float4* __restrict__ in1, float4* __restrict__ out1, int n1)
{
    const float4* in = blockIdx.y ? in1 : in0;
    float4* out = blockIdx.y ? out1 : out0;
    const int n4 = blockIdx.y ? n1 : n0;
    int i = blockIdx.x * blockDim.x + threadIdx.x;
    const int stride = gridDim.x * blockDim.x;
    for (; i < n4; i += stride) {
        float4 v = in[i];
        v.x = __uint_as_float(f2tf32(v.x));
        v.y = __uint_as_float(f2tf32(v.y));
        v.z = __uint_as_float(f2tf32(v.z));
        v.w = __uint_as_float(f2tf32(v.w));
        out[i] = v;
    }
}

// ---------------------------------------------------------------------------
// Tensor-core tf32 GEMM: C = (X @ W^T + bias) * scale
// Inputs PRE-ROUNDED to tf32; fragments via ldmatrix (24 ldmatrix + 64 mma
// per ktile, was 96 LDS + 64 mma). CTA 128x128, BK=32, 3-stage cp.async.
// ---------------------------------------------------------------------------
#define SROW 36
#define STAGE_FLOATS (2 * 128 * SROW)
#define GEMM_SMEM_BYTES (3 * STAGE_FLOATS * 4)     // 110592

template <int HEAD_LAYOUT>
__global__ __launch_bounds__(256, 2)
void gemm_tf32_kernel(const float* __restrict__ X, const float* __restrict__ W,
                      const float* __restrict__ bias, float* __restrict__ out,
                      int M, int N, int K, float scale)
{
    extern __shared__ float smem[];
    const uint32_t smem_base = (uint32_t)__cvta_generic_to_shared(smem);
    const int tid = threadIdx.x;
    const int wid = tid >> 5;
    const int lane = tid & 31;
    const int g = lane >> 2;
    const int tig = lane & 3;
    const int wm = wid >> 2;
    const int wn = wid & 3;
    const int m0 = blockIdx.y * 128;
    const int n0 = blockIdx.x * 128;
    const int KT = K >> 5;

    // ldmatrix lane roles
    const int q8 = lane >> 3;      // matrix group 0..3
    const int rr = lane & 7;       // row within matrix
    uint32_t aoff[4], boff[2];
#pragma unroll
    for (int fm = 0; fm < 4; fm++)
        aoff[fm] = (uint32_t)(((wm * 64 + fm * 16 + rr + (q8 & 1) * 8) * SROW
                               + (q8 >> 1) * 4) * 4);
#pragma unroll
    for (int p = 0; p < 2; p++)
        boff[p] = (uint32_t)((128 * SROW + (wn * 32 + p * 16 + (q8 >> 1) * 8 + rr) * SROW
                              + (q8 & 1) * 4) * 4);

    auto load_tile = [&](int tile) {
        const int k0 = tile << 5;
        const uint32_t base = smem_base + (uint32_t)(tile % 3) * (STAGE_FLOATS * 4);
#pragma unroll
        for (int i = 0; i < 4; i++) {
            int idx = tid + (i << 8);
            int r = idx >> 3;
            int c = idx & 7;
            uint32_t dst = base + (uint32_t)(r * SROW * 4 + c * 16);
            cp_async16(dst, X + (size_t)(m0 + r) * K + k0 + c * 4);
            cp_async16(dst + 128 * SROW * 4, W + (size_t)(n0 + r) * K + k0 + c * 4);
        }
    };

    load_tile(0); cp_commit();
    load_tile(1); cp_commit();

    float acc[4][4][4];
#pragma unroll
    for (int fm = 0; fm < 4; fm++)
#pragma unroll
        for (int fn = 0; fn < 4; fn++)
#pragma unroll
            for (int e = 0; e < 4; e++) acc[fm][fn][e] = 0.0f;

    for (int kt = 0; kt < KT; kt++) {
        cp_wait1();
        __syncthreads();
        if (kt + 2 < KT) load_tile(kt + 2);
        cp_commit();

        const uint32_t stage = smem_base + (uint32_t)(kt % 3) * (STAGE_FLOATS * 4);

#pragma unroll
        for (int ks = 0; ks < 4; ks++) {
            const uint32_t kso = (uint32_t)(ks * 32);
            uint32_t a[4][4], bb[2][4];
#pragma unroll
            for (int fm = 0; fm < 4; fm++) ldmat_x4(a[fm], stage + aoff[fm] + kso);
#pragma unroll
            for (int p = 0; p < 2; p++) ldmat_x4(bb[p], stage + boff[p] + kso);
#pragma unroll
            for (int fm = 0; fm < 4; fm++)
#pragma unroll
                for (int fn = 0; fn < 4; fn++)
                    mma_tf32(acc[fm][fn], a[fm], &bb[fn >> 1][(fn & 1) * 2]);
        }
    }

#pragma unroll
    for (int fm = 0; fm < 4; fm++) {
#pragma unroll
        for (int fn = 0; fn < 4; fn++) {
            int n = n0 + wn * 32 + fn * 8 + 2 * tig;
            float bx = __ldg(&bias[n]);
            float by = __ldg(&bias[n + 1]);
#pragma unroll
            for (int half = 0; half < 2; half++) {
                int m = m0 + wm * 64 + fm * 16 + g + half * 8;
                float2 o;
                o.x = (acc[fm][fn][half * 2 + 0] + bx) * scale;
                o.y = (acc[fm][fn][half * 2 + 1] + by) * scale;
                if (HEAD_LAYOUT) {
                    o.x = __uint_as_float(f2tf32(o.x));   // pre-round for flash mma
                    o.y = __uint_as_float(f2tf32(o.y));
                    int b = m / TT, t = m % TT;
                    int h = n / DKk, dk = n % DKk;
                    *(float2*)&out[(((size_t)b * HH + h) * TT + t) * DKk + dk] = o;
                } else {
                    *(float2*)&out[(size_t)m * N + n] = o;
                }
            }
        }
    }
}

// ---------------------------------------------------------------------------
// Tensor-core flash attention (causal). Q pre-scaled by 0.125*log2(e); q/k/v
// tf32-rounded. Q/K/P fragments via ldmatrix; V stays scalar LDS (needs trans).
// BQ=128, BK=32, triple-buffered KV, one __syncthreads per tile, 2 CTAs/SM.
// ---------------------------------------------------------------------------
#define QSTR 68
#define KSTR 68
#define VSTR 72
#define PSTR 36
#define OFF_K (128 * QSTR)
#define OFF_V (OFF_K + 3 * 32 * KSTR)
#define OFF_P (OFF_V + 3 * 32 * VSTR)
#define FA_SMEM_FLOATS (OFF_P + 128 * PSTR)
#define FA_SMEM_BYTES (FA_SMEM_FLOATS * 4)   // 107008

__global__ __launch_bounds__(256, 2)
void flash_tc_kernel(const float* __restrict__ Q, const float* __restrict__ K,
                     const float* __restrict__ V, float* __restrict__ out)
{
    extern __shared__ float sm[];
    const uint32_t smb = (uint32_t)__cvta_generic_to_shared(sm);
    const int tid = threadIdx.x;
    const int wid = tid >> 5;
    const int lane = tid & 31;
    const int g = lane >> 2;
    const int tig = lane & 3;
    const int qt = blockIdx.x;
    const int bh = blockIdx.y;

    const int q8 = lane >> 3;
    const int rr = lane & 7;
    const uint32_t qoff = (uint32_t)(((wid * 16 + rr + (q8 & 1) * 8) * QSTR
                                      + (q8 >> 1) * 4) * 4);
    uint32_t koff[2];
#pragma unroll
    for (int p = 0; p < 2; p++)
        koff[p] = (uint32_t)(((p * 16 + (q8 >> 1) * 8 + rr) * KSTR + (q8 & 1) * 4) * 4);
    const uint32_t poff = (uint32_t)((OFF_P + (wid * 16 + rr + (q8 & 1) * 8) * PSTR
                                      + (q8 >> 1) * 4) * 4);

    const float* Qb = Q + ((size_t)bh * TT + qt * 128) * DKk;
    const float* Kb = K + (size_t)bh * TT * DKk;
    const float* Vb = V + (size_t)bh * TT * DKk;

    // Load Q tile 128x64 (2048 float4, 8/thread)
#pragma unroll
    for (int i = 0; i < 8; i++) {
        int idx = tid + (i << 8);
        int r = idx >> 4;
        int c = idx & 15;
        cp_async16(smb + (uint32_t)((r * QSTR + c * 4) * 4), Qb + r * DKk + c * 4);
    }

    auto load_kv = [&](int kt) {
        const int buf = kt % 3;
        const float* kp = Kb + (size_t)kt * 32 * DKk;
        const float* vp = Vb + (size_t)kt * 32 * DKk;
        const uint32_t kb_ = smb + (uint32_t)((OFF_K + buf * 32 * KSTR) * 4);
        const uint32_t vb_ = smb + (uint32_t)((OFF_V + buf * 32 * VSTR) * 4);
#pragma unroll
        for (int i = 0; i < 2; i++) {
            int idx = tid + (i << 8);
            int r = idx >> 4;
            int c = idx & 15;
            cp_async16(kb_ + (uint32_t)((r * KSTR + c * 4) * 4), kp + r * DKk + c * 4);
            cp_async16(vb_ + (uint32_t)((r * VSTR + c * 4) * 4), vp + r * DKk + c * 4);
        }
    };

    load_kv(0);
    cp_commit();
    load_kv(1);
    cp_commit();

    float m0r = -1e30f, m1r = -1e30f, l0 = 0.0f, l1 = 0.0f;
    float o[8][4];
#pragma unroll
    for (int nf = 0; nf < 8; nf++)
#pragma unroll
        for (int e = 0; e < 4; e++) o[nf][e] = 0.0f;

    const int nkt = 4 * qt + 4;
    const int row0 = wid * 16 + g;
    uint32_t* Pw = (uint32_t*)(sm + OFF_P) + row0 * PSTR;

    for (int kt = 0; kt < nkt; kt++) {
        cp_wait1();
        __syncthreads();
        if (kt + 2 < nkt) load_kv(kt + 2);
        cp_commit();

        const int buf = kt % 3;
        const uint32_t kbase = smb + (uint32_t)((OFF_K + buf * 32 * KSTR) * 4);
        const uint32_t* Vs = (const uint32_t*)(sm + OFF_V + buf * 32 * VSTR);

        // ---- S = Q @ K^T (16x32 per warp) ----
        float s[4][4];
#pragma unroll
        for (int nf = 0; nf < 4; nf++)
#pragma unroll
            for (int e = 0; e < 4; e++) s[nf][e] = 0.0f;

#pragma unroll
        for (int ks = 0; ks < 8; ks++) {
            const uint32_t kso = (uint32_t)(ks * 32);
            uint32_t a[4], bb[2][4];
            ldmat_x4(a, smb + qoff + kso);
            ldmat_x4(bb[0], kbase + koff[0] + kso);
            ldmat_x4(bb[1], kbase + koff[1] + kso);
#pragma unroll
            for (int nf = 0; nf < 4; nf++)
                mma_tf32(s[nf], a, &bb[nf >> 1][(nf & 1) * 2]);
        }

        // ---- causal mask ----
        if (kt >= 4 * qt) {
            const int qg0 = qt * 128 + row0;
            const int qg1 = qg0 + 8;
#pragma unroll
            for (int nf = 0; nf < 4; nf++) {
                int kg = kt * 32 + nf * 8 + 2 * tig;
                if (kg > qg0) s[nf][0] = -1e30f;
                if (kg + 1 > qg0) s[nf][1] = -1e30f;
                if (kg > qg1) s[nf][2] = -1e30f;
                if (kg + 1 > qg1) s[nf][3] = -1e30f;
            }
        }

        // ---- online softmax (base-2) ----
        float mx0 = -1e30f, mx1 = -1e30f;
#pragma unroll
        for (int nf = 0; nf < 4; nf++) {
            mx0 = fmaxf(mx0, fmaxf(s[nf][0], s[nf][1]));
            mx1 = fmaxf(mx1, fmaxf(s[nf][2], s[nf][3]));
        }
        mx0 = fmaxf(mx0, __shfl_xor_sync(0xffffffffu, mx0, 1));
        mx0 = fmaxf(mx0, __shfl_xor_sync(0xffffffffu, mx0, 2));
        mx1 = fmaxf(mx1, __shfl_xor_sync(0xffffffffu, mx1, 1));
        mx1 = fmaxf(mx1, __shfl_xor_sync(0xffffffffu, mx1, 2));

        float mn0 = fmaxf(m0r, mx0);
        float mn1 = fmaxf(m1r, mx1);
        float al0 = exp2f(m0r - mn0);
        float al1 = exp2f(m1r - mn1);
        m0r = mn0; m1r = mn1;

        float sum0 = 0.0f, sum1 = 0.0f;
#pragma unroll
        for (int nf = 0; nf < 4; nf++) {
            s[nf][0] = exp2f(s[nf][0] - mn0); sum0 += s[nf][0];
            s[nf][1] = exp2f(s[nf][1] - mn0); sum0 += s[nf][1];
            s[nf][2] = exp2f(s[nf][2] - mn1); sum1 += s[nf][2];
            s[nf][3] = exp2f(s[nf][3] - mn1); sum1 += s[nf][3];
        }
        sum0 += __shfl_xor_sync(0xffffffffu, sum0, 1);
        sum0 += __shfl_xor_sync(0xffffffffu, sum0, 2);
        sum1 += __shfl_xor_sync(0xffffffffu, sum1, 1);
        sum1 += __shfl_xor_sync(0xffffffffu, sum1, 2);
        l0 = l0 * al0 + sum0;
        l1 = l1 * al1 + sum1;

#pragma unroll
        for (int nf = 0; nf < 8; nf++) {
            o[nf][0] *= al0; o[nf][1] *= al0;
            o[nf][2] *= al1; o[nf][3] *= al1;
        }

        // ---- store P (tf32-rounded) to warp-private smem ----
#pragma unroll
        for (int nf = 0; nf < 4; nf++) {
            int c = nf * 8 + 2 * tig;
            Pw[c] = f2tf32(s[nf][0]);
            Pw[c + 1] = f2tf32(s[nf][1]);
            Pw[8 * PSTR + c] = f2tf32(s[nf][2]);
            Pw[8 * PSTR + c + 1] = f2tf32(s[nf][3]);
        }
        __syncwarp();

        // ---- O += P @ V (16x64 per warp) ----
#pragma unroll
        for (int ks = 0; ks < 4; ks++) {
            const int kb = ks * 8;
            uint32_t a[4];
            ldmat_x4(a, smb + poff + (uint32_t)(ks * 32));
            const uint32_t* vr = Vs + (kb + tig) * VSTR + g;
#pragma unroll
            for (int nf = 0; nf < 8; nf++) {
                uint32_t b[2];
                b[0] = vr[nf * 8];
                b[1] = vr[4 * VSTR + nf * 8];
                mma_tf32(o[nf], a, b);
            }
        }
    }

    // ---- epilogue: O /= l, tf32-round (for cvt-free final GEMM), write ----
    const int b = bh >> 4;
    const int h = bh & 15;
    const float li0 = 1.0f / l0;
    const float li1 = 1.0f / l1;
    const int qg0 = qt * 128 + row0;
#pragma unroll
    for (int nf = 0; nf < 8; nf++) {
        int col = h * DKk + nf * 8 + 2 * tig;
        float2 o0, o1;
        o0.x = __uint_as_float(f2tf32(o[nf][0] * li0));
        o0.y = __uint_as_float(f2tf32(o[nf][1] * li0));
        o1.x = __uint_as_float(f2tf32(o[nf][2] * li1));
        o1.y = __uint_as_float(f2tf32(o[nf][3] * li1));
        *(float2*)&out[((size_t)b * TT + qg0) * DM + col] = o0;
        *(float2*)&out[((size_t)b * TT + qg0 + 8) * DM + col] = o1;
    }
}

// ---------------------------------------------------------------------------
extern "C" void kernel_launch(void* const* d_in, const int* in_sizes, int n_in,
                              void* d_out, int out_size)
{
    const float* query = (const float*)d_in[0];
    const float* key   = (const float*)d_in[1];
    const float* value = (const float*)d_in[2];
    // d_in[3] = mask (causal tril, known statically — unused)
    const float* Wq = (const float*)d_in[4];
    const float* bq = (const float*)d_in[5];
    const float* Wk = (const float*)d_in[6];
    const float* bk = (const float*)d_in[7];
    const float* Wv = (const float*)d_in[8];
    const float* bv = (const float*)d_in[9];
    const float* Wo = (const float*)d_in[10];
    const float* bo = (const float*)d_in[11];
    float* out = (float*)d_out;

    float *q, *k, *v, *ao, *xq, *xk, *xv, *wq, *wk, *wv, *wo;
    cudaGetSymbolAddress((void**)&q,  g_q);
    cudaGetSymbolAddress((void**)&k,  g_k);
    cudaGetSymbolAddress((void**)&v,  g_v);
    cudaGetSymbolAddress((void**)&ao, g_ao);
    cudaGetSymbolAddress((void**)&xq, g_xq);
    cudaGetSymbolAddress((void**)&xk, g_xk);
    cudaGetSymbolAddress((void**)&xv, g_xv);
    cudaGetSymbolAddress((void**)&wq, g_wq);
    cudaGetSymbolAddress((void**)&wk, g_wk);
    cudaGetSymbolAddress((void**)&wv, g_wv);
    cudaGetSymbolAddress((void**)&wo, g_wo);

    cudaFuncSetAttribute(gemm_tf32_kernel<1>,
                         cudaFuncAttributeMaxDynamicSharedMemorySize, GEMM_SMEM_BYTES);
    cudaFuncSetAttribute(gemm_tf32_kernel<0>,
                         cudaFuncAttributeMaxDynamicSharedMemorySize, GEMM_SMEM_BYTES);
    cudaFuncSetAttribute(flash_tc_kernel,
                         cudaFuncAttributeMaxDynamicSharedMemorySize, FA_SMEM_BYTES);

    // Streams/events created once on the first (non-captured) correctness call;
    // reused by the capture call via the standard event fork/join pattern.
    static cudaStream_t s1 = nullptr, s2 = nullptr, s3 = nullptr;
    static cudaEvent_t ef = nullptr, ej1 = nullptr, ej2 = nullptr, ej3 = nullptr;
    if (!s1) {
        cudaStreamCreateWithFlags(&s1, cudaStreamNonBlocking);
        cudaStreamCreateWithFlags(&s2, cudaStreamNonBlocking);
        cudaStreamCreateWithFlags(&s3, cudaStreamNonBlocking);
        cudaEventCreateWithFlags(&ef,  cudaEventDisableTiming);
        cudaEventCreateWithFlags(&ej1, cudaEventDisableTiming);
        cudaEventCreateWithFlags(&ej2, cudaEventDisableTiming);
        cudaEventCreateWithFlags(&ej3, cudaEventDisableTiming);
    }

    const int M = BB * TT;               // 8192
    const int NX4 = M * DM / 4;          // 2M float4
    const int NW4 = DM * DM / 4;         // 256K float4
    dim3 gemm_grid(DM / 128, M / 128);   // (8, 64)
    dim3 rgrid(512, 2);
    const float qscale = 0.125f * 1.4426950408889634f;

    // Fork: s1/s2/s3 depend on everything previously enqueued on stream 0
    cudaEventRecord(ef, 0);
    cudaStreamWaitEvent(s1, ef, 0);
    cudaStreamWaitEvent(s2, ef, 0);
    cudaStreamWaitEvent(s3, ef, 0);

    // Q chain (stream 0)
    round2_kernel<<<rgrid, 256, 0, 0>>>((const float4*)query, (float4*)xq, NX4,
                                        (const float4*)Wq, (float4*)wq, NW4);
    gemm_tf32_kernel<1><<<gemm_grid, 256, GEMM_SMEM_BYTES, 0>>>(xq, wq, bq, q, M, DM, DM, qscale);

    // K chain (s1)
    round2_kernel<<<rgrid, 256, 0, s1>>>((const float4*)key, (float4*)xk, NX4,
                                         (const float4*)Wk, (float4*)wk, NW4);
    gemm_tf32_kernel<1><<<gemm_grid, 256, GEMM_SMEM_BYTES, s1>>>(xk, wk, bk, k, M, DM, DM, 1.0f);
    cudaEventRecord(ej1, s1);

    // V chain (s2)
    round2_kernel<<<rgrid, 256, 0, s2>>>((const float4*)value, (float4*)xv, NX4,
                                         (const float4*)Wv, (float4*)wv, NW4);
    gemm_tf32_kernel<1><<<gemm_grid, 256, GEMM_SMEM_BYTES, s2>>>(xv, wv, bv, v, M, DM, DM, 1.0f);
    cudaEventRecord(ej2, s2);

    // Wo rounding (s3) — only needed by the final GEMM
    round2_kernel<<<dim3(512, 1), 256, 0, s3>>>((const float4*)Wo, (float4*)wo, NW4,
                                                (const float4*)Wo, (float4*)wo, 0);
    cudaEventRecord(ej3, s3);

    // Join K and V before flash
    cudaStreamWaitEvent(0, ej1, 0);
    cudaStreamWaitEvent(0, ej2, 0);

    // Tensor-core flash attention (causal)
    dim3 fa_grid(TT / 128, BB * HH);     // (16, 64)
    flash_tc_kernel<<<fa_grid, 256, FA_SMEM_BYTES, 0>>>(q, k, v, ao);

    // Output projection (waits for Wo rounding)
    cudaStreamWaitEvent(0, ej3, 0);
    gemm_tf32_kernel<0><<<gemm_grid, 256, GEMM_SMEM_BYTES, 0>>>(ao, wo, bo, out, M, DM, DM, 1.0f);
}

// round 7
// speedup vs baseline: 6.7032x; 1.6390x over previous
#include <cuda_runtime.h>
#include <cuda_fp16.h>
#include <cstdint>

#define BB 4
#define TT 2048
#define HH 16
#define DKk 64
#define DM 1024

// Scratch (static device globals: allocation-free, graph-capture safe)
__device__ __half g_q[BB * HH * TT * DKk];   // [B,H,T,Dk], scaled by 0.125*log2(e)
__device__ __half g_k[BB * HH * TT * DKk];
__device__ __half g_v[BB * HH * TT * DKk];
__device__ __half g_ao[BB * TT * DM];        // [B,T,D]
// fp16 copies of GEMM inputs
__device__ __half g_xq[BB * TT * DM];
__device__ __half g_xk[BB * TT * DM];
__device__ __half g_xv[BB * TT * DM];
__device__ __half g_wq[DM * DM];
__device__ __half g_wk[DM * DM];
__device__ __half g_wv[DM * DM];
__device__ __half g_wo[DM * DM];

// ---------------------------------------------------------------------------
// Baseline-PTX helpers (harness ptxas targets plain sm_103: no tcgen05;
// mma.sync m16n8k16 f16 + cp.async + ldmatrix are fine)
// ---------------------------------------------------------------------------
__device__ __forceinline__ void cp_async16(uint32_t s, const void* g) {
    asm volatile("cp.async.cg.shared.global [%0], [%1], 16;\n" :: "r"(s), "l"(g));
}
__device__ __forceinline__ void cp_commit() {
    asm volatile("cp.async.commit_group;\n" ::: "memory");
}
__device__ __forceinline__ void cp_wait1() {
    asm volatile("cp.async.wait_group 1;\n" ::: "memory");
}

__device__ __forceinline__ void ldmat_x4(uint32_t* r, uint32_t addr) {
    asm volatile("ldmatrix.sync.aligned.m8n8.x4.shared.b16 {%0,%1,%2,%3}, [%4];"
                 : "=r"(r[0]), "=r"(r[1]), "=r"(r[2]), "=r"(r[3]) : "r"(addr));
}
__device__ __forceinline__ void ldmat_x4_t(uint32_t* r, uint32_t addr) {
    asm volatile("ldmatrix.sync.aligned.m8n8.x4.trans.shared.b16 {%0,%1,%2,%3}, [%4];"
                 : "=r"(r[0]), "=r"(r[1]), "=r"(r[2]), "=r"(r[3]) : "r"(addr));
}

// D += A(16x16 f16, row) * B(16x8 f16, col), fp32 accumulate
__device__ __forceinline__ void mma_f16(float* c, const uint32_t* a, const uint32_t* b) {
    asm volatile(
        "mma.sync.aligned.m16n8k16.row.col.f32.f16.f16.f32 "
        "{%0,%1,%2,%3}, {%4,%5,%6,%7}, {%8,%9}, {%0,%1,%2,%3};"
        : "+f"(c[0]), "+f"(c[1]), "+f"(c[2]), "+f"(c[3])
        : "r"(a[0]), "r"(a[1]), "r"(a[2]), "r"(a[3]), "r"(b[0]), "r"(b[1]));
}

// ---------------------------------------------------------------------------
// fp32 -> fp16 conversion pre-pass: two arrays per launch (blockIdx.y selects)
// ---------------------------------------------------------------------------
__global__ __launch_bounds__(256)
void cvt2_kernel(const float4* __restrict__ in0, __half2* __restrict__ out0, int n0,
                 const float4* __restrict__ in1, __half2* __restrict__ out1, int n1)
{
    const float4* in = blockIdx.y ? in1 : in0;
    __half2* out = blockIdx.y ? out1 : out0;
    const int n4 = blockIdx.y ? n1 : n0;
    int i = blockIdx.x * blockDim.x + threadIdx.x;
    const int stride = gridDim.x * blockDim.x;
    for (; i < n4; i += stride) {
        float4 v = in[i];
        out[2 * i + 0] = __floats2half2_rn(v.x, v.y);
        out[2 * i + 1] = __floats2half2_rn(v.z, v.w);
    }
}

// ---------------------------------------------------------------------------
// Tensor-core fp16 GEMM: C = (X @ W^T + bias) * scale
// X: [M,K] fp16 rm.  W: [N,K] fp16 rm (== col-major B for row.col mma).
// CTA 128x128, BK=32, 3-stage cp.async, 8 warps (2x4), warp tile 64x32.
// Smem pad: 40 halves/row (80B, 16B-aligned, ldmatrix bank-conflict-free).
// HEAD_LAYOUT=1: fp16 scatter to [B,H,T,Dk]; else fp32 row-major [M,N].
// ---------------------------------------------------------------------------
#define AROW 40
#define A_HALVES (128 * AROW)               // 5120
#define STG_HALVES (2 * A_HALVES)           // 10240
#define GEMM_SMEM_BYTES (3 * STG_HALVES * 2)  // 61440

template <int HEAD_LAYOUT>
__global__ __launch_bounds__(256, 2)
void gemm_f16_kernel(const __half* __restrict__ X, const __half* __restrict__ W,
                     const float* __restrict__ bias, void* __restrict__ outv,
                     int M, int N, int K, float scale)
{
    extern __shared__ __half smh[];
    const uint32_t smem_base = (uint32_t)__cvta_generic_to_shared(smh);
    const int tid = threadIdx.x;
    const int wid = tid >> 5;
    const int lane = tid & 31;
    const int g = lane >> 2;
    const int tig = lane & 3;
    const int q8 = lane >> 3;
    const int rr = lane & 7;
    const int wm = wid >> 2;
    const int wn = wid & 3;
    const int m0 = blockIdx.y * 128;
    const int n0 = blockIdx.x * 128;
    const int KT = K >> 5;

    // ldmatrix base offsets (halves)
    uint32_t aoff[4], boff[2];
#pragma unroll
    for (int fm = 0; fm < 4; fm++)
        aoff[fm] = (uint32_t)((wm * 64 + fm * 16 + (q8 & 1) * 8 + rr) * AROW + (q8 >> 1) * 8);
#pragma unroll
    for (int p = 0; p < 2; p++)
        boff[p] = (uint32_t)(A_HALVES + (wn * 32 + p * 16 + (q8 & 1) * 8 + rr) * AROW + (q8 >> 1) * 8);

    auto load_tile = [&](int tile) {
        const int k0 = tile << 5;
        const uint32_t base = smem_base + (uint32_t)(tile % 3) * (STG_HALVES * 2);
#pragma unroll
        for (int i = 0; i < 2; i++) {
            int idx = tid + (i << 8);          // 0..511
            int r = idx >> 2;                  // 0..127
            int c = idx & 3;                   // chunk 0..3 (8 halves each)
            uint32_t dst = base + (uint32_t)((r * AROW + c * 8) * 2);
            cp_async16(dst, X + (size_t)(m0 + r) * K + k0 + c * 8);
            cp_async16(dst + A_HALVES * 2, W + (size_t)(n0 + r) * K + k0 + c * 8);
        }
    };

    load_tile(0); cp_commit();
    load_tile(1); cp_commit();

    float acc[4][4][4];
#pragma unroll
    for (int fm = 0; fm < 4; fm++)
#pragma unroll
        for (int fn = 0; fn < 4; fn++)
#pragma unroll
            for (int e = 0; e < 4; e++) acc[fm][fn][e] = 0.0f;

    for (int kt = 0; kt < KT; kt++) {
        cp_wait1();
        __syncthreads();
        if (kt + 2 < KT) load_tile(kt + 2);
        cp_commit();

        const uint32_t stage = smem_base + (uint32_t)(kt % 3) * (STG_HALVES * 2);

#pragma unroll
        for (int ks = 0; ks < 2; ks++) {
            const uint32_t kso = (uint32_t)(ks * 16 * 2);   // bytes
            uint32_t a[4][4], bb[2][4];
#pragma unroll
            for (int fm = 0; fm < 4; fm++) ldmat_x4(a[fm], stage + aoff[fm] * 2 + kso);
#pragma unroll
            for (int p = 0; p < 2; p++) ldmat_x4(bb[p], stage + boff[p] * 2 + kso);
#pragma unroll
            for (int fm = 0; fm < 4; fm++)
#pragma unroll
                for (int fn = 0; fn < 4; fn++) {
                    uint32_t b2[2] = {bb[fn >> 1][fn & 1], bb[fn >> 1][2 + (fn & 1)]};
                    mma_f16(acc[fm][fn], a[fm], b2);
                }
        }
    }

#pragma unroll
    for (int fm = 0; fm < 4; fm++) {
#pragma unroll
        for (int fn = 0; fn < 4; fn++) {
            int n = n0 + wn * 32 + fn * 8 + 2 * tig;
            float bx = __ldg(&bias[n]);
            float by = __ldg(&bias[n + 1]);
#pragma unroll
            for (int half = 0; half < 2; half++) {
                int m = m0 + wm * 64 + fm * 16 + g + half * 8;
                float ox = (acc[fm][fn][half * 2 + 0] + bx) * scale;
                float oy = (acc[fm][fn][half * 2 + 1] + by) * scale;
                if (HEAD_LAYOUT) {
                    __half* out = (__half*)outv;
                    int b = m / TT, t = m % TT;
                    int h = n / DKk, dk = n % DKk;
                    *(__half2*)&out[(((size_t)b * HH + h) * TT + t) * DKk + dk] =
                        __floats2half2_rn(ox, oy);
                } else {
                    float* out = (float*)outv;
                    *(float2*)&out[(size_t)m * N + n] = make_float2(ox, oy);
                }
            }
        }
    }
}

// ---------------------------------------------------------------------------
// Tensor-core fp16 flash attention (causal). Q pre-scaled by 0.125*log2(e).
// BQ=128, BK=32, triple-buffered KV, one __syncthreads per tile, 8 warps.
// Q/K/V: 64-half rows, XOR swizzle chunk^(row%8) (conflict-free, no padding).
// P: 40-half padded rows. smem = 51200 B -> 2 CTAs/SM (reg-limited anyway).
// ---------------------------------------------------------------------------
#define Q_OFF 0
#define K_OFF (128 * 64)                    // 8192
#define V_OFF (K_OFF + 3 * 32 * 64)          // 14336
#define P_OFF (V_OFF + 3 * 32 * 64)          // 20480
#define FA_HALVES (P_OFF + 128 * 40)         // 25600
#define FA_SMEM_BYTES (FA_HALVES * 2)        // 51200

__global__ __launch_bounds__(256, 2)
void flash_f16_kernel(const __half* __restrict__ Q, const __half* __restrict__ K,
                      const __half* __restrict__ V, __half* __restrict__ out)
{
    extern __shared__ __half smh[];
    const uint32_t smb = (uint32_t)__cvta_generic_to_shared(smh);
    const int tid = threadIdx.x;
    const int wid = tid >> 5;
    const int lane = tid & 31;
    const int g = lane >> 2;
    const int tig = lane & 3;
    const int q8 = lane >> 3;
    const int rr = lane & 7;
    const int qc = q8 >> 1;
    const int rb = (q8 & 1) * 8;
    const int qt = blockIdx.x;
    const int bh = blockIdx.y;

    const __half* Qb = Q + ((size_t)bh * TT + qt * 128) * DKk;
    const __half* Kb = K + (size_t)bh * TT * DKk;
    const __half* Vb = V + (size_t)bh * TT * DKk;

    // Load Q tile 128x64 halves, swizzled (1024 chunks, 4/thread)
#pragma unroll
    for (int i = 0; i < 4; i++) {
        int idx = tid + (i << 8);
        int r = idx >> 3;
        int c = idx & 7;
        uint32_t dst = smb + (uint32_t)((r * 64 + ((c ^ (r & 7)) * 8)) * 2);
        cp_async16(dst, Qb + r * 64 + c * 8);
    }

    auto load_kv = [&](int kt) {
        const int buf = kt % 3;
        const __half* kp = Kb + (size_t)kt * 32 * DKk;
        const __half* vp = Vb + (size_t)kt * 32 * DKk;
        int r = tid >> 3;          // 0..31
        int c = tid & 7;
        uint32_t off = (uint32_t)((r * 64 + ((c ^ (r & 7)) * 8)) * 2);
        uint32_t src_off = (uint32_t)(r * 64 + c * 8);
        cp_async16(smb + (K_OFF + buf * 2048) * 2 + off, kp + src_off);
        cp_async16(smb + (V_OFF + buf * 2048) * 2 + off, vp + src_off);
    };

    load_kv(0);
    cp_commit();
    load_kv(1);
    cp_commit();

    float m0r = -1e30f, m1r = -1e30f, l0 = 0.0f, l1 = 0.0f;
    float o[8][4];
#pragma unroll
    for (int nf = 0; nf < 8; nf++)
#pragma unroll
        for (int e = 0; e < 4; e++) o[nf][e] = 0.0f;

    const int nkt = 4 * qt + 4;
    const int row0 = wid * 16 + g;

    // fragment row bases (halves)
    const uint32_t qrow_h = (uint32_t)((wid * 16 + rb + rr) * 64);
    const uint32_t prow_h = (uint32_t)(P_OFF + (wid * 16 + rb + rr) * 40 + qc * 8);

    for (int kt = 0; kt < nkt; kt++) {
        cp_wait1();
        __syncthreads();
        if (kt + 2 < nkt) load_kv(kt + 2);
        cp_commit();

        const int buf = kt % 3;
        const uint32_t kbuf_h = (uint32_t)(K_OFF + buf * 2048);
        const uint32_t vbuf_h = (uint32_t)(V_OFF + buf * 2048);

        // ---- S = Q @ K^T (16x32 per warp), dk = 64 -> 4 ksteps of k16 ----
        float s[4][4];
#pragma unroll
        for (int nf = 0; nf < 4; nf++)
#pragma unroll
            for (int e = 0; e < 4; e++) s[nf][e] = 0.0f;

#pragma unroll
        for (int ks = 0; ks < 4; ks++) {
            uint32_t a[4], bb[2][4];
            const uint32_t ch = (uint32_t)(((2 * ks + qc) ^ rr) * 8);
            ldmat_x4(a, smb + (qrow_h + ch) * 2);
#pragma unroll
            for (int p = 0; p < 2; p++) {
                uint32_t krow_h = kbuf_h + (uint32_t)((p * 16 + rb + rr) * 64);
                ldmat_x4(bb[p], smb + (krow_h + ch) * 2);
            }
#pragma unroll
            for (int nf = 0; nf < 4; nf++) {
                uint32_t b2[2] = {bb[nf >> 1][nf & 1], bb[nf >> 1][2 + (nf & 1)]};
                mma_f16(s[nf], a, b2);
            }
        }

        // ---- causal mask ----
        if (kt >= 4 * qt) {
            const int qg0 = qt * 128 + row0;
            const int qg1 = qg0 + 8;
#pragma unroll
            for (int nf = 0; nf < 4; nf++) {
                int kg = kt * 32 + nf * 8 + 2 * tig;
                if (kg > qg0) s[nf][0] = -1e30f;
                if (kg + 1 > qg0) s[nf][1] = -1e30f;
                if (kg > qg1) s[nf][2] = -1e30f;
                if (kg + 1 > qg1) s[nf][3] = -1e30f;
            }
        }

        // ---- online softmax (base-2) ----
        float mx0 = -1e30f, mx1 = -1e30f;
#pragma unroll
        for (int nf = 0; nf < 4; nf++) {
            mx0 = fmaxf(mx0, fmaxf(s[nf][0], s[nf][1]));
            mx1 = fmaxf(mx1, fmaxf(s[nf][2], s[nf][3]));
        }
        mx0 = fmaxf(mx0, __shfl_xor_sync(0xffffffffu, mx0, 1));
        mx0 = fmaxf(mx0, __shfl_xor_sync(0xffffffffu, mx0, 2));
        mx1 = fmaxf(mx1, __shfl_xor_sync(0xffffffffu, mx1, 1));
        mx1 = fmaxf(mx1, __shfl_xor_sync(0xffffffffu, mx1, 2));

        float mn0 = fmaxf(m0r, mx0);
        float mn1 = fmaxf(m1r, mx1);
        float al0 = exp2f(m0r - mn0);
        float al1 = exp2f(m1r - mn1);
        m0r = mn0; m1r = mn1;

        float sum0 = 0.0f, sum1 = 0.0f;
#pragma unroll
        for (int nf = 0; nf < 4; nf++) {
            s[nf][0] = exp2f(s[nf][0] - mn0); sum0 += s[nf][0];
            s[nf][1] = exp2f(s[nf][1] - mn0); sum0 += s[nf][1];
            s[nf][2] = exp2f(s[nf][2] - mn1); sum1 += s[nf][2];
            s[nf][3] = exp2f(s[nf][3] - mn1); sum1 += s[nf][3];
        }
        sum0 += __shfl_xor_sync(0xffffffffu, sum0, 1);
        sum0 += __shfl_xor_sync(0xffffffffu, sum0, 2);
        sum1 += __shfl_xor_sync(0xffffffffu, sum1, 1);
        sum1 += __shfl_xor_sync(0xffffffffu, sum1, 2);
        l0 = l0 * al0 + sum0;
        l1 = l1 * al1 + sum1;

#pragma unroll
        for (int nf = 0; nf < 8; nf++) {
            o[nf][0] *= al0; o[nf][1] *= al0;
            o[nf][2] *= al1; o[nf][3] *= al1;
        }

        // ---- store P (fp16) to warp-private padded smem ----
#pragma unroll
        for (int nf = 0; nf < 4; nf++) {
            int c = nf * 8 + 2 * tig;
            *(__half2*)&smh[P_OFF + (wid * 16 + g) * 40 + c] =
                __floats2half2_rn(s[nf][0], s[nf][1]);
            *(__half2*)&smh[P_OFF + (wid * 16 + g + 8) * 40 + c] =
                __floats2half2_rn(s[nf][2], s[nf][3]);
        }
        __syncwarp();

        // ---- O += P @ V (16x64 per warp), kv 32 -> 2 ksteps of k16 ----
#pragma unroll
        for (int ks = 0; ks < 2; ks++) {
            uint32_t pa[4];
            ldmat_x4(pa, smb + (prow_h + (uint32_t)(ks * 16)) * 2);
            const uint32_t vrow_h = vbuf_h + (uint32_t)((16 * ks + rb + rr) * 64);
#pragma unroll
            for (int p = 0; p < 4; p++) {
                uint32_t vv[4];
                const uint32_t ch = (uint32_t)(((2 * p + qc) ^ rr) * 8);
                ldmat_x4_t(vv, smb + (vrow_h + ch) * 2);
                mma_f16(o[2 * p + 0], pa, &vv[0]);
                mma_f16(o[2 * p + 1], pa, &vv[2]);
            }
        }
    }

    // ---- epilogue: O /= l, fp16 write [B,T,D] ----
    const int b = bh >> 4;
    const int h = bh & 15;
    const float li0 = 1.0f / l0;
    const float li1 = 1.0f / l1;
    const int qg0 = qt * 128 + row0;
#pragma unroll
    for (int nf = 0; nf < 8; nf++) {
        int col = h * DKk + nf * 8 + 2 * tig;
        *(__half2*)&out[((size_t)b * TT + qg0) * DM + col] =
            __floats2half2_rn(o[nf][0] * li0, o[nf][1] * li0);
        *(__half2*)&out[((size_t)b * TT + qg0 + 8) * DM + col] =
            __floats2half2_rn(o[nf][2] * li1, o[nf][3] * li1);
    }
}

// ---------------------------------------------------------------------------
extern "C" void kernel_launch(void* const* d_in, const int* in_sizes, int n_in,
                              void* d_out, int out_size)
{
    const float* query = (const float*)d_in[0];
    const float* key   = (const float*)d_in[1];
    const float* value = (const float*)d_in[2];
    // d_in[3] = mask (causal tril, known statically — unused)
    const float* Wq = (const float*)d_in[4];
    const float* bq = (const float*)d_in[5];
    const float* Wk = (const float*)d_in[6];
    const float* bk = (const float*)d_in[7];
    const float* Wv = (const float*)d_in[8];
    const float* bv = (const float*)d_in[9];
    const float* Wo = (const float*)d_in[10];
    const float* bo = (const float*)d_in[11];
    float* out = (float*)d_out;

    __half *q, *k, *v, *ao, *xq, *xk, *xv, *wq, *wk, *wv, *wo;
    cudaGetSymbolAddress((void**)&q,  g_q);
    cudaGetSymbolAddress((void**)&k,  g_k);
    cudaGetSymbolAddress((void**)&v,  g_v);
    cudaGetSymbolAddress((void**)&ao, g_ao);
    cudaGetSymbolAddress((void**)&xq, g_xq);
    cudaGetSymbolAddress((void**)&xk, g_xk);
    cudaGetSymbolAddress((void**)&xv, g_xv);
    cudaGetSymbolAddress((void**)&wq, g_wq);
    cudaGetSymbolAddress((void**)&wk, g_wk);
    cudaGetSymbolAddress((void**)&wv, g_wv);
    cudaGetSymbolAddress((void**)&wo, g_wo);

    cudaFuncSetAttribute(gemm_f16_kernel<1>,
                         cudaFuncAttributeMaxDynamicSharedMemorySize, GEMM_SMEM_BYTES);
    cudaFuncSetAttribute(gemm_f16_kernel<0>,
                         cudaFuncAttributeMaxDynamicSharedMemorySize, GEMM_SMEM_BYTES);
    cudaFuncSetAttribute(flash_f16_kernel,
                         cudaFuncAttributeMaxDynamicSharedMemorySize, FA_SMEM_BYTES);

    static cudaStream_t s1 = nullptr, s2 = nullptr, s3 = nullptr;
    static cudaEvent_t ef = nullptr, ej1 = nullptr, ej2 = nullptr, ej3 = nullptr;
    if (!s1) {
        cudaStreamCreateWithFlags(&s1, cudaStreamNonBlocking);
        cudaStreamCreateWithFlags(&s2, cudaStreamNonBlocking);
        cudaStreamCreateWithFlags(&s3, cudaStreamNonBlocking);
        cudaEventCreateWithFlags(&ef,  cudaEventDisableTiming);
        cudaEventCreateWithFlags(&ej1, cudaEventDisableTiming);
        cudaEventCreateWithFlags(&ej2, cudaEventDisableTiming);
        cudaEventCreateWithFlags(&ej3, cudaEventDisableTiming);
    }

    const int M = BB * TT;               // 8192
    const int NX4 = M * DM / 4;
    const int NW4 = DM * DM / 4;
    dim3 gemm_grid(DM / 128, M / 128);   // (8, 64)
    dim3 rgrid(512, 2);
    const float qscale = 0.125f * 1.4426950408889634f;

    // Fork
    cudaEventRecord(ef, 0);
    cudaStreamWaitEvent(s1, ef, 0);
    cudaStreamWaitEvent(s2, ef, 0);
    cudaStreamWaitEvent(s3, ef, 0);

    // Q chain (stream 0)
    cvt2_kernel<<<rgrid, 256, 0, 0>>>((const float4*)query, (__half2*)xq, NX4,
                                      (const float4*)Wq, (__half2*)wq, NW4);
    gemm_f16_kernel<1><<<gemm_grid, 256, GEMM_SMEM_BYTES, 0>>>(xq, wq, bq, q, M, DM, DM, qscale);

    // K chain (s1)
    cvt2_kernel<<<rgrid, 256, 0, s1>>>((const float4*)key, (__half2*)xk, NX4,
                                       (const float4*)Wk, (__half2*)wk, NW4);
    gemm_f16_kernel<1><<<gemm_grid, 256, GEMM_SMEM_BYTES, s1>>>(xk, wk, bk, k, M, DM, DM, 1.0f);
    cudaEventRecord(ej1, s1);

    // V chain (s2)
    cvt2_kernel<<<rgrid, 256, 0, s2>>>((const float4*)value, (__half2*)xv, NX4,
                                       (const float4*)Wv, (__half2*)wv, NW4);
    gemm_f16_kernel<1><<<gemm_grid, 256, GEMM_SMEM_BYTES, s2>>>(xv, wv, bv, v, M, DM, DM, 1.0f);
    cudaEventRecord(ej2, s2);

    // Wo conversion (s3)
    cvt2_kernel<<<dim3(512, 1), 256, 0, s3>>>((const float4*)Wo, (__half2*)wo, NW4,
                                              (const float4*)Wo, (__half2*)wo, 0);
    cudaEventRecord(ej3, s3);

    // Join K and V before flash
    cudaStreamWaitEvent(0, ej1, 0);
    cudaStreamWaitEvent(0, ej2, 0);

    dim3 fa_grid(TT / 128, BB * HH);     // (16, 64)
    flash_f16_kernel<<<fa_grid, 256, FA_SMEM_BYTES, 0>>>(q, k, v, ao);

    // Output projection
    cudaStreamWaitEvent(0, ej3, 0);
    gemm_f16_kernel<0><<<gemm_grid, 256, GEMM_SMEM_BYTES, 0>>>(ao, wo, bo, out, M, DM, DM, 1.0f);
}